// round 3
// baseline (speedup 1.0000x reference)
#include <cuda_runtime.h>
#include <cstdint>

#define Bb 2
#define Vv 4
#define Cc 64
#define Hh 256
#define Ww 256
#define Nn (Hh * Ww)       // 65536
#define BV (Bb * Vv)       // 8
#define EPSF 1e-8f

// ---------------- scratch (device globals: allocation-free per harness rules) ----
__device__ float g_featsT[(size_t)BV * Nn * Cc];  // feats transposed to (BV, N, C)  128MB
__device__ float g_acc[(size_t)BV * Nn * Cc];     // accumulator (BV, N, C)          128MB
__device__ float g_wz[(size_t)BV * Nn * 2];       // per-target (wsum, wz)             4MB
// per-bv matrices (exact fp32): [Kinv(16), srcRTinv(16), dstRT(16), K(16)]
__device__ float g_mats[BV * 64];

// Exact fp32 4x4 matvec, fma chain ascending j (XLA dot lowering order).
__device__ __forceinline__ void mv4(const float* __restrict__ M,
                                    const float v[4], float o[4]) {
#pragma unroll
    for (int r = 0; r < 4; r++) {
        float s = __fmul_rn(M[r * 4 + 0], v[0]);
        s = __fmaf_rn(M[r * 4 + 1], v[1], s);
        s = __fmaf_rn(M[r * 4 + 2], v[2], s);
        s = __fmaf_rn(M[r * 4 + 3], v[3], s);
        o[r] = s;
    }
}

// ---------------- 4x4 inverse (Gauss-Jordan, partial pivot; exact for this K) ---
__device__ void inv4(const float* a, float* o) {
    float m[4][8];
    for (int r = 0; r < 4; r++)
        for (int c = 0; c < 4; c++) {
            m[r][c] = a[r * 4 + c];
            m[r][4 + c] = (r == c) ? 1.f : 0.f;
        }
    for (int col = 0; col < 4; col++) {
        int piv = col;
        for (int r = col + 1; r < 4; r++)
            if (fabsf(m[r][col]) > fabsf(m[piv][col])) piv = r;
        if (piv != col)
            for (int c = 0; c < 8; c++) { float t = m[col][c]; m[col][c] = m[piv][c]; m[piv][c] = t; }
        float s = __fdiv_rn(1.f, m[col][col]);
        for (int c = 0; c < 8; c++) m[col][c] = __fmul_rn(m[col][c], s);
        for (int r = 0; r < 4; r++) {
            if (r == col) continue;
            float f = m[r][col];
            for (int c = 0; c < 8; c++) m[r][c] = __fmaf_rn(-f, m[col][c], m[r][c]);
        }
    }
    for (int r = 0; r < 4; r++)
        for (int c = 0; c < 4; c++) o[r * 4 + c] = m[r][4 + c];
}

// Store exact fp32 matrices per bv: Kinv, srcRTinv, dstRT, K.
__global__ void build_mats_kernel(const float* __restrict__ K,
                                  const float* __restrict__ srcRTinv,
                                  const float* __restrict__ dstRT) {
    int bv = threadIdx.x;
    if (bv >= BV) return;
    int b = bv / Vv;
    float Kb[16], Ki[16];
    for (int i = 0; i < 16; i++) Kb[i] = K[b * 16 + i];
    inv4(Kb, Ki);
    float* out = &g_mats[bv * 64];
    for (int i = 0; i < 16; i++) {
        out[i]      = Ki[i];
        out[16 + i] = srcRTinv[bv * 16 + i];
        out[32 + i] = dstRT[b * 16 + i];   // dst_RTs is (B,1,4,4)
        out[48 + i] = Kb[i];
    }
}

// ---------------- zero accumulators --------------------------------------------
__global__ void zero_kernel() {
    const size_t stride = (size_t)gridDim.x * blockDim.x;
    size_t i = (size_t)blockIdx.x * blockDim.x + threadIdx.x;
    float4 z = make_float4(0.f, 0.f, 0.f, 0.f);
    float4* acc4 = reinterpret_cast<float4*>(g_acc);
    const size_t na = (size_t)BV * Nn * Cc / 4;
    for (size_t j = i; j < na; j += stride) acc4[j] = z;
    float4* wz4 = reinterpret_cast<float4*>(g_wz);
    const size_t nw = (size_t)BV * Nn * 2 / 4;
    for (size_t j = i; j < nw; j += stride) wz4[j] = z;
}

// ---------------- transpose feats (BV,C,N) -> (BV,N,C) --------------------------
__global__ void transpose_kernel(const float* __restrict__ in) {
    __shared__ float tile[32][33];
    int bv = blockIdx.z;
    int c0 = blockIdx.y * 32;
    int n0 = blockIdx.x * 32;
    const float* ip = in + (size_t)bv * Cc * Nn;
    float* op = g_featsT + (size_t)bv * Nn * Cc;
    int tx = threadIdx.x, ty = threadIdx.y;
#pragma unroll
    for (int i = 0; i < 32; i += 8)
        tile[ty + i][tx] = ip[(size_t)(c0 + ty + i) * Nn + n0 + tx];
    __syncthreads();
#pragma unroll
    for (int i = 0; i < 32; i += 8)
        op[(size_t)(n0 + ty + i) * Cc + c0 + tx] = tile[tx][ty + i];
}

// ---------------- splat: one warp per source pixel ------------------------------
// Half-warp h (lanes 0-15 / 16-31) processes taps t = 2*i + h; each lane handles
// 4 channels via red.global.add.v4.f32 into channel-contiguous accumulator.
__global__ void __launch_bounds__(256) splat_kernel(const float* __restrict__ depths) {
    int w = (int)((blockIdx.x * blockDim.x + threadIdx.x) >> 5);
    int lane = threadIdx.x & 31;
    int bv = w >> 16;            // N = 65536
    int n = w & (Nn - 1);
    float gx = (float)(n & (Ww - 1));
    float gy = (float)(n >> 8);

    float d = __ldg(&depths[w]);
    const float* M = &g_mats[bv * 64];

    // Exact fp32 reference chain: xyp = K*(dstRT*(srcRTinv*(Kinv*proj)))
    float pr[4] = {__fmul_rn(gx, d), __fmul_rn(gy, d), d, 1.f};
    float cam[4], wld[4], c2[4], xyp[4];
    mv4(M + 0,  pr,  cam);
    mv4(M + 16, cam, wld);
    mv4(M + 32, wld, c2);
    mv4(M + 48, c2,  xyp);

    float Z = xyp[2];
    float zeps = __fadd_rn(Z, EPSF);
    float x = __fdiv_rn(xyp[0], zeps);   // reference: xyp0 / (z + eps)
    float y = __fdiv_rn(xyp[1], zeps);
    float invz = __frcp_rn(zeps);        // reference: 1.0 / (z + eps), div.rn
    float px0 = rintf(x);                // matches jnp.round (half-to-even)
    float py0 = rintf(y);
    bool zok = (Z > EPSF);

    int h = lane >> 4;       // half-warp id: tap parity
    int sl = lane & 15;      // sub-lane: channel group
    float4 f = *reinterpret_cast<const float4*>(&g_featsT[((size_t)w << 6) + 4 * sl]);
    float* accbase = g_acc + ((size_t)bv * Nn << 6);
    float* wzbase = g_wz + ((size_t)bv * Nn << 1);

#pragma unroll
    for (int i = 0; i < 13; i++) {
        int t = 2 * i + h;
        int dyi = t / 5 - 2;
        int dxi = t % 5 - 2;
        float px = __fadd_rn(px0, (float)dxi);
        float py = __fadd_rn(py0, (float)dyi);
        float ddx = __fadd_rn(px, -x);
        float ddy = __fadd_rn(py, -y);
        float s2 = __fadd_rn(__fadd_rn(__fmul_rn(ddx, ddx), __fmul_rn(ddy, ddy)), 1e-8f);
        float dist = __fsqrt_rn(s2);
        float wgt = __fadd_rn(1.0f, -__fmul_rn(dist, 0.5f));  // 1 - dist/RADIUS
        bool live = (t < 25) && zok && (wgt > 0.f) &&
                    (px >= 0.f) && (px < (float)Ww) && (py >= 0.f) && (py < (float)Hh);
        if (live) {
            wgt = __fmul_rn(wgt, invz);
            int idx = ((int)py << 8) + (int)px;
            float* p = accbase + ((size_t)idx << 6) + 4 * sl;
            asm volatile("red.global.add.v4.f32 [%0], {%1,%2,%3,%4};" ::
                         "l"(p), "f"(__fmul_rn(wgt, f.x)), "f"(__fmul_rn(wgt, f.y)),
                         "f"(__fmul_rn(wgt, f.z)), "f"(__fmul_rn(wgt, f.w)) : "memory");
            if (sl == 0) {
                float* q = wzbase + ((size_t)idx << 1);
                asm volatile("red.global.add.v2.f32 [%0], {%1,%2};" ::
                             "l"(q), "f"(wgt), "f"(__fmul_rn(wgt, Z)) : "memory");
            }
        }
    }
}

// ---------------- normalize + transpose back to (BV, C+1, N) --------------------
__global__ void __launch_bounds__(256) normalize_kernel(float* __restrict__ out) {
    __shared__ float tile[64][33];
    __shared__ float ws[32];
    __shared__ float zs[32];
    int bv = blockIdx.y;
    int n0 = blockIdx.x * 32;
    int tid = threadIdx.x;

    const float* acc = g_acc + (((size_t)bv * Nn + n0) << 6);
    for (int l = tid; l < 32 * 64; l += 256) {
        int p = l >> 6;
        int c = l & 63;
        tile[c][p] = acc[l];   // acc[p*64+c] == acc[l]
    }
    if (tid < 32) {
        float2 wzv = *reinterpret_cast<const float2*>(&g_wz[((size_t)(bv * Nn + n0 + tid)) << 1]);
        ws[tid] = __fadd_rn(wzv.x, EPSF);
        zs[tid] = wzv.y;
    }
    __syncthreads();

    float* ob = out + (size_t)bv * (Cc + 1) * Nn + n0;
    for (int l = tid; l < 32 * 64; l += 256) {
        int c = l >> 5;
        int p = l & 31;
        ob[(size_t)c * Nn + p] = __fdiv_rn(tile[c][p], ws[p]);
    }
    if (tid < 32) ob[(size_t)Cc * Nn + tid] = __fdiv_rn(zs[tid], ws[tid]);
}

// ---------------- launch ---------------------------------------------------------
extern "C" void kernel_launch(void* const* d_in, const int* in_sizes, int n_in,
                              void* d_out, int out_size) {
    const float* feats    = (const float*)d_in[0];
    const float* depths   = (const float*)d_in[1];
    const float* K        = (const float*)d_in[2];
    const float* srcRTinv = (const float*)d_in[4];
    const float* dstRT    = (const float*)d_in[5];
    float* out = (float*)d_out;

    build_mats_kernel<<<1, 32>>>(K, srcRTinv, dstRT);
    zero_kernel<<<8192, 256>>>();
    transpose_kernel<<<dim3(Nn / 32, Cc / 32, BV), dim3(32, 8)>>>(feats);
    splat_kernel<<<(BV * Nn * 32) / 256, 256>>>(depths);
    normalize_kernel<<<dim3(Nn / 32, BV), 256>>>(out);
}

// round 5
// speedup vs baseline: 1.3045x; 1.3045x over previous
#include <cuda_runtime.h>
#include <cstdint>

#define Bb 2
#define Vv 4
#define Cc 64
#define Hh 256
#define Ww 256
#define Nn (Hh * Ww)       // 65536
#define BV (Bb * Vv)       // 8
#define EPSF 1e-8f

// ---------------- scratch (device globals: allocation-free per harness rules) ----
__device__ float g_featsT[(size_t)BV * Nn * Cc];  // feats transposed to (BV, N, C)  128MB
__device__ float g_acc[(size_t)BV * Nn * Cc];     // accumulator (BV, N, C)          128MB
__device__ float g_wz[(size_t)BV * Nn * 2];       // per-target (wsum, wz)             4MB
// per-bv matrices (exact fp32): [Kinv(16), srcRTinv(16), dstRT(16), K(16)]
__device__ float g_mats[BV * 64];

// 21 live taps of the 5x5 footprint (4 corners provably dead: dist >= 2.12 > 2),
// padded to 22 with a dummy dead tap. Slot j = 2*i + halfwarp.
__device__ constexpr float TDX[22] = {-1.f,0.f,1.f,-2.f,-1.f,0.f,1.f,2.f,-2.f,-1.f,0.f,1.f,2.f,
                                      -2.f,-1.f,0.f,1.f,2.f,-1.f,0.f,1.f,1e9f};
__device__ constexpr float TDY[22] = {-2.f,-2.f,-2.f,-1.f,-1.f,-1.f,-1.f,-1.f,0.f,0.f,0.f,0.f,0.f,
                                      1.f,1.f,1.f,1.f,1.f,2.f,2.f,2.f,1e9f};
__device__ constexpr int   TOFF[22] = {-513,-512,-511,-258,-257,-256,-255,-254,-2,-1,0,1,2,
                                       254,255,256,257,258,511,512,513,0};

// Exact fp32 4x4 matvec, fma chain ascending j (matches XLA dot lowering order).
__device__ __forceinline__ void mv4(const float4* __restrict__ M,
                                    const float v[4], float o[4]) {
#pragma unroll
    for (int r = 0; r < 4; r++) {
        float4 m = __ldg(&M[r]);
        float s = __fmul_rn(m.x, v[0]);
        s = __fmaf_rn(m.y, v[1], s);
        s = __fmaf_rn(m.z, v[2], s);
        s = __fmaf_rn(m.w, v[3], s);
        o[r] = s;
    }
}

// ---------------- 4x4 inverse (Gauss-Jordan, partial pivot) ---------------------
__device__ void inv4(const float* a, float* o) {
    float m[4][8];
    for (int r = 0; r < 4; r++)
        for (int c = 0; c < 4; c++) {
            m[r][c] = a[r * 4 + c];
            m[r][4 + c] = (r == c) ? 1.f : 0.f;
        }
    for (int col = 0; col < 4; col++) {
        int piv = col;
        for (int r = col + 1; r < 4; r++)
            if (fabsf(m[r][col]) > fabsf(m[piv][col])) piv = r;
        if (piv != col)
            for (int c = 0; c < 8; c++) { float t = m[col][c]; m[col][c] = m[piv][c]; m[piv][c] = t; }
        float s = __fdiv_rn(1.f, m[col][col]);
        for (int c = 0; c < 8; c++) m[col][c] = __fmul_rn(m[col][c], s);
        for (int r = 0; r < 4; r++) {
            if (r == col) continue;
            float f = m[r][col];
            for (int c = 0; c < 8; c++) m[r][c] = __fmaf_rn(-f, m[col][c], m[r][c]);
        }
    }
    for (int r = 0; r < 4; r++)
        for (int c = 0; c < 4; c++) o[r * 4 + c] = m[r][4 + c];
}

__global__ void build_mats_kernel(const float* __restrict__ K,
                                  const float* __restrict__ srcRTinv,
                                  const float* __restrict__ dstRT) {
    int bv = threadIdx.x;
    if (bv >= BV) return;
    int b = bv / Vv;
    float Kb[16], Ki[16];
    for (int i = 0; i < 16; i++) Kb[i] = K[b * 16 + i];
    inv4(Kb, Ki);
    float* out = &g_mats[bv * 64];
    for (int i = 0; i < 16; i++) {
        out[i]      = Ki[i];
        out[16 + i] = srcRTinv[bv * 16 + i];
        out[32 + i] = dstRT[b * 16 + i];   // dst_RTs is (B,1,4,4)
        out[48 + i] = Kb[i];
    }
}

// ---------------- zero accumulators --------------------------------------------
__global__ void zero_kernel() {
    const size_t stride = (size_t)gridDim.x * blockDim.x;
    size_t i = (size_t)blockIdx.x * blockDim.x + threadIdx.x;
    float4 z = make_float4(0.f, 0.f, 0.f, 0.f);
    float4* acc4 = reinterpret_cast<float4*>(g_acc);
    const size_t na = (size_t)BV * Nn * Cc / 4;
    for (size_t j = i; j < na; j += stride) acc4[j] = z;
    float4* wz4 = reinterpret_cast<float4*>(g_wz);
    const size_t nw = (size_t)BV * Nn * 2 / 4;
    for (size_t j = i; j < nw; j += stride) wz4[j] = z;
}

// ---------------- transpose feats (BV,C,N) -> (BV,N,C) --------------------------
__global__ void transpose_kernel(const float* __restrict__ in) {
    __shared__ float tile[32][33];
    int bv = blockIdx.z;
    int c0 = blockIdx.y * 32;
    int n0 = blockIdx.x * 32;
    const float* ip = in + (size_t)bv * Cc * Nn;
    float* op = g_featsT + (size_t)bv * Nn * Cc;
    int tx = threadIdx.x, ty = threadIdx.y;
#pragma unroll
    for (int i = 0; i < 32; i += 8)
        tile[ty + i][tx] = ip[(size_t)(c0 + ty + i) * Nn + n0 + tx];
    __syncthreads();
#pragma unroll
    for (int i = 0; i < 32; i += 8)
        op[(size_t)(n0 + ty + i) * Cc + c0 + tx] = tile[tx][ty + i];
}

// ---------------- tap loop (templated on bounds checking) -----------------------
template <bool CHECK>
__device__ __forceinline__ void do_taps(float fx, float fy, float invz, float Z,
                                        float* accp, float* wzp, float4 f,
                                        bool hb, bool sl0, float px0, float py0) {
#pragma unroll
    for (int i = 0; i < 11; i++) {
        float dxf = hb ? TDX[2 * i + 1] : TDX[2 * i];
        float dyf = hb ? TDY[2 * i + 1] : TDY[2 * i];
        int off   = hb ? TOFF[2 * i + 1] : TOFF[2 * i];
        float ddx = dxf + fx;
        float ddy = dyf + fy;
        float s2 = __fmaf_rn(ddx, ddx, __fmaf_rn(ddy, ddy, EPSF));
        float dist;
        asm("sqrt.approx.f32 %0, %1;" : "=f"(dist) : "f"(s2));
        float wgt = __fmaf_rn(dist, -0.5f, 1.0f);   // == 1 - dist*0.5 exactly
        bool live = wgt > 0.f;
        if (CHECK) {
            float px = px0 + dxf;
            float py = py0 + dyf;
            live = live && (px >= 0.f) && (px < (float)Ww) &&
                           (py >= 0.f) && (py < (float)Hh);
        }
        if (live) {
            float ws = __fmul_rn(wgt, invz);
            float* p = accp + ((long)off << 6);
            asm volatile("red.global.add.v4.f32 [%0], {%1,%2,%3,%4};" ::
                         "l"(p), "f"(__fmul_rn(ws, f.x)), "f"(__fmul_rn(ws, f.y)),
                         "f"(__fmul_rn(ws, f.z)), "f"(__fmul_rn(ws, f.w)) : "memory");
            if (sl0) {
                float* q = wzp + ((long)off << 1);
                asm volatile("red.global.add.v2.f32 [%0], {%1,%2};" ::
                             "l"(q), "f"(ws), "f"(__fmul_rn(ws, Z)) : "memory");
            }
        }
    }
}

// ---------------- splat: one warp per source pixel ------------------------------
__global__ void __launch_bounds__(256) splat_kernel(const float* __restrict__ depths) {
    int w = (int)((blockIdx.x * blockDim.x + threadIdx.x) >> 5);
    int lane = threadIdx.x & 31;
    int bv = w >> 16;            // N = 65536
    int n = w & (Nn - 1);
    float gx = (float)(n & (Ww - 1));
    float gy = (float)(n >> 8);

    float d = __ldg(&depths[w]);
    const float* M = &g_mats[bv * 64];

    // Exact fp32 reference chain: xyp = K*(dstRT*(srcRTinv*(Kinv*proj)))
    float pr[4] = {__fmul_rn(gx, d), __fmul_rn(gy, d), d, 1.f};
    float cam[4], wld[4], c2[4], xyp[4];
    mv4((const float4*)(M + 0),  pr,  cam);
    mv4((const float4*)(M + 16), cam, wld);
    mv4((const float4*)(M + 32), wld, c2);
    mv4((const float4*)(M + 48), c2,  xyp);

    float Z = xyp[2];
    if (!(Z > EPSF)) return;               // warp-uniform; ref adds w=0 -> no-op
    float zeps = __fadd_rn(Z, EPSF);
    float x = __fdiv_rn(xyp[0], zeps);     // reference: xyp0 / (z + eps)
    float y = __fdiv_rn(xyp[1], zeps);
    float invz = __frcp_rn(zeps);          // reference: 1.0 / (z + eps)
    float px0 = rintf(x);                  // matches jnp.round (half-to-even)
    float py0 = rintf(y);

    float fx = px0 - x;                    // feeds approx dist only
    float fy = py0 - y;
    int ix0 = (int)px0;                    // exact: px0 integral
    int iy0 = (int)py0;
    long idx_base = (long)iy0 * Ww + ix0;

    bool hb = lane >= 16;        // half-warp id: tap parity
    int sl = lane & 15;          // sub-lane: channel group
    bool sl0 = (sl == 0);
    float4 f = *reinterpret_cast<const float4*>(&g_featsT[((size_t)w << 6) + 4 * sl]);
    float* accp = g_acc + (((long)bv << 22) + (idx_base << 6) + 4 * sl);
    float* wzp  = g_wz  + (((long)bv << 17) + (idx_base << 1));

    bool interior = (px0 >= 2.f) && (px0 <= (float)(Ww - 3)) &&
                    (py0 >= 2.f) && (py0 <= (float)(Hh - 3));
    if (interior)
        do_taps<false>(fx, fy, invz, Z, accp, wzp, f, hb, sl0, px0, py0);
    else
        do_taps<true>(fx, fy, invz, Z, accp, wzp, f, hb, sl0, px0, py0);
}

// ---------------- normalize + transpose back to (BV, C+1, N) --------------------
__global__ void __launch_bounds__(256) normalize_kernel(float* __restrict__ out) {
    __shared__ float tile[64][33];
    __shared__ float ws[32];
    __shared__ float zs[32];
    int bv = blockIdx.y;
    int n0 = blockIdx.x * 32;
    int tid = threadIdx.x;

    const float* acc = g_acc + (((size_t)bv * Nn + n0) << 6);
    for (int l = tid; l < 32 * 64; l += 256) {
        int p = l >> 6;
        int c = l & 63;
        tile[c][p] = acc[l];   // acc[p*64+c] == acc[l]
    }
    if (tid < 32) {
        float2 wzv = *reinterpret_cast<const float2*>(&g_wz[((size_t)(bv * Nn + n0 + tid)) << 1]);
        ws[tid] = __fadd_rn(wzv.x, EPSF);
        zs[tid] = wzv.y;
    }
    __syncthreads();

    float* ob = out + (size_t)bv * (Cc + 1) * Nn + n0;
    for (int l = tid; l < 32 * 64; l += 256) {
        int c = l >> 5;
        int p = l & 31;
        ob[(size_t)c * Nn + p] = __fdiv_rn(tile[c][p], ws[p]);
    }
    if (tid < 32) ob[(size_t)Cc * Nn + tid] = __fdiv_rn(zs[tid], ws[tid]);
}

// ---------------- launch ---------------------------------------------------------
extern "C" void kernel_launch(void* const* d_in, const int* in_sizes, int n_in,
                              void* d_out, int out_size) {
    const float* feats    = (const float*)d_in[0];
    const float* depths   = (const float*)d_in[1];
    const float* K        = (const float*)d_in[2];
    const float* srcRTinv = (const float*)d_in[4];
    const float* dstRT    = (const float*)d_in[5];
    float* out = (float*)d_out;

    build_mats_kernel<<<1, 32>>>(K, srcRTinv, dstRT);
    zero_kernel<<<8192, 256>>>();
    transpose_kernel<<<dim3(Nn / 32, Cc / 32, BV), dim3(32, 8)>>>(feats);
    splat_kernel<<<(BV * Nn * 32) / 256, 256>>>(depths);
    normalize_kernel<<<dim3(Nn / 32, BV), 256>>>(out);
}

// round 6
// speedup vs baseline: 1.3466x; 1.0323x over previous
#include <cuda_runtime.h>
#include <cstdint>

#define Bb 2
#define Vv 4
#define Cc 64
#define Hh 256
#define Ww 256
#define Nn (Hh * Ww)       // 65536
#define BV (Bb * Vv)       // 8
#define EPSF 1e-8f

// ---------------- scratch (device globals: allocation-free per harness rules) ----
__device__ float g_featsT[(size_t)BV * Nn * Cc];  // feats transposed to (BV, N, C)  128MB
__device__ float g_acc[(size_t)BV * Nn * Cc];     // accumulator (BV, N, C)          128MB
__device__ float g_wz[(size_t)BV * Nn * 2];       // per-target (wsum, wz)             4MB
__device__ float4 g_xyz[(size_t)BV * Nn];         // per-pixel {x, y, invz, Z}         8MB
// per-bv matrices (exact fp32): [Kinv(16), srcRTinv(16), dstRT(16), K(16)]
__device__ float g_mats[BV * 64];

// 21 live taps of the 5x5 footprint (4 corners provably dead: dist >= 2.12 > 2),
// padded to 22 with a dummy dead tap. Slot j = 2*i + halfwarp.
__device__ constexpr float TDX[22] = {-1.f,0.f,1.f,-2.f,-1.f,0.f,1.f,2.f,-2.f,-1.f,0.f,1.f,2.f,
                                      -2.f,-1.f,0.f,1.f,2.f,-1.f,0.f,1.f,1e9f};
__device__ constexpr float TDY[22] = {-2.f,-2.f,-2.f,-1.f,-1.f,-1.f,-1.f,-1.f,0.f,0.f,0.f,0.f,0.f,
                                      1.f,1.f,1.f,1.f,1.f,2.f,2.f,2.f,1e9f};
__device__ constexpr int   TOFF[22] = {-513,-512,-511,-258,-257,-256,-255,-254,-2,-1,0,1,2,
                                       254,255,256,257,258,511,512,513,0};

// Exact fp32 4x4 matvec, fma chain ascending j (matches XLA dot lowering order).
__device__ __forceinline__ void mv4(const float4* __restrict__ M,
                                    const float v[4], float o[4]) {
#pragma unroll
    for (int r = 0; r < 4; r++) {
        float4 m = __ldg(&M[r]);
        float s = __fmul_rn(m.x, v[0]);
        s = __fmaf_rn(m.y, v[1], s);
        s = __fmaf_rn(m.z, v[2], s);
        s = __fmaf_rn(m.w, v[3], s);
        o[r] = s;
    }
}

// ---------------- 4x4 inverse (Gauss-Jordan, partial pivot) ---------------------
__device__ void inv4(const float* a, float* o) {
    float m[4][8];
    for (int r = 0; r < 4; r++)
        for (int c = 0; c < 4; c++) {
            m[r][c] = a[r * 4 + c];
            m[r][4 + c] = (r == c) ? 1.f : 0.f;
        }
    for (int col = 0; col < 4; col++) {
        int piv = col;
        for (int r = col + 1; r < 4; r++)
            if (fabsf(m[r][col]) > fabsf(m[piv][col])) piv = r;
        if (piv != col)
            for (int c = 0; c < 8; c++) { float t = m[col][c]; m[col][c] = m[piv][c]; m[piv][c] = t; }
        float s = __fdiv_rn(1.f, m[col][col]);
        for (int c = 0; c < 8; c++) m[col][c] = __fmul_rn(m[col][c], s);
        for (int r = 0; r < 4; r++) {
            if (r == col) continue;
            float f = m[r][col];
            for (int c = 0; c < 8; c++) m[r][c] = __fmaf_rn(-f, m[col][c], m[r][c]);
        }
    }
    for (int r = 0; r < 4; r++)
        for (int c = 0; c < 4; c++) o[r * 4 + c] = m[r][4 + c];
}

__global__ void build_mats_kernel(const float* __restrict__ K,
                                  const float* __restrict__ srcRTinv,
                                  const float* __restrict__ dstRT) {
    int bv = threadIdx.x;
    if (bv >= BV) return;
    int b = bv / Vv;
    float Kb[16], Ki[16];
    for (int i = 0; i < 16; i++) Kb[i] = K[b * 16 + i];
    inv4(Kb, Ki);
    float* out = &g_mats[bv * 64];
    for (int i = 0; i < 16; i++) {
        out[i]      = Ki[i];
        out[16 + i] = srcRTinv[bv * 16 + i];
        out[32 + i] = dstRT[b * 16 + i];   // dst_RTs is (B,1,4,4)
        out[48 + i] = Kb[i];
    }
}

// ---------------- projection precompute (1 thread / pixel) + zero g_wz -----------
__global__ void __launch_bounds__(256) proj_kernel(const float* __restrict__ depths) {
    int w = blockIdx.x * blockDim.x + threadIdx.x;   // BV*Nn threads
    // fused: zero wz (one float2 per thread)
    reinterpret_cast<float2*>(g_wz)[w] = make_float2(0.f, 0.f);

    int bv = w >> 16;
    int n = w & (Nn - 1);
    float gx = (float)(n & (Ww - 1));
    float gy = (float)(n >> 8);

    float d = __ldg(&depths[w]);
    const float* M = &g_mats[bv * 64];

    // Exact fp32 reference chain: xyp = K*(dstRT*(srcRTinv*(Kinv*proj)))
    float pr[4] = {__fmul_rn(gx, d), __fmul_rn(gy, d), d, 1.f};
    float cam[4], wld[4], c2[4], xyp[4];
    mv4((const float4*)(M + 0),  pr,  cam);
    mv4((const float4*)(M + 16), cam, wld);
    mv4((const float4*)(M + 32), wld, c2);
    mv4((const float4*)(M + 48), c2,  xyp);

    float Z = xyp[2];
    float zeps = __fadd_rn(Z, EPSF);
    float x = __fdiv_rn(xyp[0], zeps);     // reference: xyp0 / (z + eps)
    float y = __fdiv_rn(xyp[1], zeps);
    float invz = __frcp_rn(zeps);          // reference: 1.0 / (z + eps)
    g_xyz[w] = make_float4(x, y, invz, Z);
}

// ---------------- transpose feats (BV,C,N) -> (BV,N,C), fused zero of g_acc ------
__global__ void transpose_kernel(const float* __restrict__ in) {
    __shared__ float tile[32][33];
    int bv = blockIdx.z;
    int c0 = blockIdx.y * 32;
    int n0 = blockIdx.x * 32;
    const float* ip = in + (size_t)bv * Cc * Nn;
    float* op = g_featsT + (size_t)bv * Nn * Cc;
    int tx = threadIdx.x, ty = threadIdx.y;

    // fused: zero acc (1 float4 per thread; 32768 blocks x 256 threads == 8M float4)
    size_t zid = ((size_t)((blockIdx.z * gridDim.y + blockIdx.y) * gridDim.x + blockIdx.x)) * 256
                 + ty * 32 + tx;
    reinterpret_cast<float4*>(g_acc)[zid] = make_float4(0.f, 0.f, 0.f, 0.f);

#pragma unroll
    for (int i = 0; i < 32; i += 8)
        tile[ty + i][tx] = ip[(size_t)(c0 + ty + i) * Nn + n0 + tx];
    __syncthreads();
#pragma unroll
    for (int i = 0; i < 32; i += 8)
        op[(size_t)(n0 + ty + i) * Cc + c0 + tx] = tile[tx][ty + i];
}

// ---------------- tap loop (templated on bounds checking) -----------------------
template <bool CHECK>
__device__ __forceinline__ void do_taps(float fx, float fy, float invz, float Z,
                                        float* accp, float* wzp, float4 f,
                                        bool hb, bool sl0, float px0, float py0) {
    float nhiz = __fmul_rn(invz, -0.5f);   // exact
#pragma unroll
    for (int i = 0; i < 11; i++) {
        float dxf = hb ? TDX[2 * i + 1] : TDX[2 * i];
        float dyf = hb ? TDY[2 * i + 1] : TDY[2 * i];
        int off   = hb ? TOFF[2 * i + 1] : TOFF[2 * i];
        float ddx = dxf + fx;
        float ddy = dyf + fy;
        float s2 = __fmaf_rn(ddx, ddx, __fmaf_rn(ddy, ddy, EPSF));
        float dist;
        asm("sqrt.approx.f32 %0, %1;" : "=f"(dist) : "f"(s2));
        // ws = (1 - dist/2) * invz, fused; sign(ws) == sign(1 - dist/2) since invz>0
        float ws = __fmaf_rn(dist, nhiz, invz);
        bool live = ws > 0.f;
        if (CHECK) {
            float px = px0 + dxf;
            float py = py0 + dyf;
            live = live && (px >= 0.f) && (px < (float)Ww) &&
                           (py >= 0.f) && (py < (float)Hh);
        }
        if (live) {
            float* p = accp + ((long)off << 6);
            asm volatile("red.global.add.v4.f32 [%0], {%1,%2,%3,%4};" ::
                         "l"(p), "f"(__fmul_rn(ws, f.x)), "f"(__fmul_rn(ws, f.y)),
                         "f"(__fmul_rn(ws, f.z)), "f"(__fmul_rn(ws, f.w)) : "memory");
            if (sl0) {
                float* q = wzp + ((long)off << 1);
                asm volatile("red.global.add.v2.f32 [%0], {%1,%2};" ::
                             "l"(q), "f"(ws), "f"(__fmul_rn(ws, Z)) : "memory");
            }
        }
    }
}

// ---------------- splat: one warp per source pixel ------------------------------
__global__ void __launch_bounds__(256, 8) splat_kernel() {
    int w = (int)((blockIdx.x * blockDim.x + threadIdx.x) >> 5);
    int lane = threadIdx.x & 31;
    int bv = w >> 16;            // N = 65536

    float4 pj = __ldg(&g_xyz[w]);    // {x, y, invz, Z} — warp-uniform broadcast
    float Z = pj.w;
    if (!(Z > EPSF)) return;         // warp-uniform; ref adds w=0 -> no-op
    float x = pj.x, y = pj.y, invz = pj.z;
    float px0 = rintf(x);            // matches jnp.round (half-to-even)
    float py0 = rintf(y);

    float fx = px0 - x;              // feeds approx dist only
    float fy = py0 - y;
    int ix0 = (int)px0;              // exact: px0 integral
    int iy0 = (int)py0;
    long idx_base = (long)iy0 * Ww + ix0;

    bool hb = lane >= 16;        // half-warp id: tap parity
    int sl = lane & 15;          // sub-lane: channel group
    bool sl0 = (sl == 0);
    float4 f = *reinterpret_cast<const float4*>(&g_featsT[((size_t)w << 6) + 4 * sl]);
    float* accp = g_acc + (((long)bv << 22) + (idx_base << 6) + 4 * sl);
    float* wzp  = g_wz  + (((long)bv << 17) + (idx_base << 1));

    bool interior = (px0 >= 2.f) && (px0 <= (float)(Ww - 3)) &&
                    (py0 >= 2.f) && (py0 <= (float)(Hh - 3));
    if (interior)
        do_taps<false>(fx, fy, invz, Z, accp, wzp, f, hb, sl0, px0, py0);
    else
        do_taps<true>(fx, fy, invz, Z, accp, wzp, f, hb, sl0, px0, py0);
}

// ---------------- normalize + transpose back to (BV, C+1, N) --------------------
__global__ void __launch_bounds__(256) normalize_kernel(float* __restrict__ out) {
    __shared__ float tile[64][33];
    __shared__ float ws[32];
    __shared__ float zs[32];
    int bv = blockIdx.y;
    int n0 = blockIdx.x * 32;
    int tid = threadIdx.x;

    const float* acc = g_acc + (((size_t)bv * Nn + n0) << 6);
    for (int l = tid; l < 32 * 64; l += 256) {
        int p = l >> 6;
        int c = l & 63;
        tile[c][p] = acc[l];   // acc[p*64+c] == acc[l]
    }
    if (tid < 32) {
        float2 wzv = *reinterpret_cast<const float2*>(&g_wz[((size_t)(bv * Nn + n0 + tid)) << 1]);
        ws[tid] = __fadd_rn(wzv.x, EPSF);
        zs[tid] = wzv.y;
    }
    __syncthreads();

    float* ob = out + (size_t)bv * (Cc + 1) * Nn + n0;
    for (int l = tid; l < 32 * 64; l += 256) {
        int c = l >> 5;
        int p = l & 31;
        ob[(size_t)c * Nn + p] = __fdiv_rn(tile[c][p], ws[p]);
    }
    if (tid < 32) ob[(size_t)Cc * Nn + tid] = __fdiv_rn(zs[tid], ws[tid]);
}

// ---------------- launch ---------------------------------------------------------
extern "C" void kernel_launch(void* const* d_in, const int* in_sizes, int n_in,
                              void* d_out, int out_size) {
    const float* feats    = (const float*)d_in[0];
    const float* depths   = (const float*)d_in[1];
    const float* K        = (const float*)d_in[2];
    const float* srcRTinv = (const float*)d_in[4];
    const float* dstRT    = (const float*)d_in[5];
    float* out = (float*)d_out;

    build_mats_kernel<<<1, 32>>>(K, srcRTinv, dstRT);
    proj_kernel<<<(BV * Nn) / 256, 256>>>(depths);                       // + zeroes g_wz
    transpose_kernel<<<dim3(Nn / 32, Cc / 32, BV), dim3(32, 8)>>>(feats); // + zeroes g_acc
    splat_kernel<<<(BV * Nn * 32) / 256, 256>>>();
    normalize_kernel<<<dim3(Nn / 32, BV), 256>>>(out);
}

// round 7
// speedup vs baseline: 1.3677x; 1.0156x over previous
#include <cuda_runtime.h>
#include <cstdint>

#define Bb 2
#define Vv 4
#define Cc 64
#define Hh 256
#define Ww 256
#define Nn (Hh * Ww)       // 65536
#define BV (Bb * Vv)       // 8
#define EPSF 1e-8f

// ---------------- scratch (device globals: allocation-free per harness rules) ----
__device__ float g_featsT[(size_t)BV * Nn * Cc];  // feats transposed to (BV, N, C)  128MB
__device__ float g_acc[(size_t)BV * Nn * Cc];     // accumulator (BV, N, C)          128MB
__device__ float g_wz[(size_t)BV * Nn * 2];       // per-target (wsum, wz)             4MB
__device__ float4 g_xyz[(size_t)BV * Nn];         // per-pixel {x, y, invz, Z}         8MB
// per-bv matrices (exact fp32): [Kinv(16), srcRTinv(16), dstRT(16), K(16)]
__device__ float g_mats[BV * 64];

// 21 live taps of the 5x5 footprint (4 corners provably dead: dist >= 2.12 > 2).
// Half-warp phase-A tables: padded to 22, slot j = 2*i + halfwarp.
__device__ constexpr float TDX[22] = {-1.f,0.f,1.f,-2.f,-1.f,0.f,1.f,2.f,-2.f,-1.f,0.f,1.f,2.f,
                                      -2.f,-1.f,0.f,1.f,2.f,-1.f,0.f,1.f,1e9f};
__device__ constexpr float TDY[22] = {-2.f,-2.f,-2.f,-1.f,-1.f,-1.f,-1.f,-1.f,0.f,0.f,0.f,0.f,0.f,
                                      1.f,1.f,1.f,1.f,1.f,2.f,2.f,2.f,1e9f};
__device__ constexpr int   TOFF[22] = {-513,-512,-511,-258,-257,-256,-255,-254,-2,-1,0,1,2,
                                       254,255,256,257,258,511,512,513,0};
// Lane-indexed (row-major) phase-B tables in global memory (LDG broadcast-friendly).
static __device__ const float LDXt[21] = {-1.f,0.f,1.f,-2.f,-1.f,0.f,1.f,2.f,-2.f,-1.f,0.f,1.f,2.f,
                                          -2.f,-1.f,0.f,1.f,2.f,-1.f,0.f,1.f};
static __device__ const float LDYt[21] = {-2.f,-2.f,-2.f,-1.f,-1.f,-1.f,-1.f,-1.f,0.f,0.f,0.f,0.f,0.f,
                                          1.f,1.f,1.f,1.f,1.f,2.f,2.f,2.f};
static __device__ const int   LOFFt[21] = {-513,-512,-511,-258,-257,-256,-255,-254,-2,-1,0,1,2,
                                           254,255,256,257,258,511,512,513};

// Exact fp32 4x4 matvec, fma chain ascending j (matches XLA dot lowering order).
__device__ __forceinline__ void mv4(const float4* __restrict__ M,
                                    const float v[4], float o[4]) {
#pragma unroll
    for (int r = 0; r < 4; r++) {
        float4 m = __ldg(&M[r]);
        float s = __fmul_rn(m.x, v[0]);
        s = __fmaf_rn(m.y, v[1], s);
        s = __fmaf_rn(m.z, v[2], s);
        s = __fmaf_rn(m.w, v[3], s);
        o[r] = s;
    }
}

// ---------------- 4x4 inverse (Gauss-Jordan, partial pivot) ---------------------
__device__ void inv4(const float* a, float* o) {
    float m[4][8];
    for (int r = 0; r < 4; r++)
        for (int c = 0; c < 4; c++) {
            m[r][c] = a[r * 4 + c];
            m[r][4 + c] = (r == c) ? 1.f : 0.f;
        }
    for (int col = 0; col < 4; col++) {
        int piv = col;
        for (int r = col + 1; r < 4; r++)
            if (fabsf(m[r][col]) > fabsf(m[piv][col])) piv = r;
        if (piv != col)
            for (int c = 0; c < 8; c++) { float t = m[col][c]; m[col][c] = m[piv][c]; m[piv][c] = t; }
        float s = __fdiv_rn(1.f, m[col][col]);
        for (int c = 0; c < 8; c++) m[col][c] = __fmul_rn(m[col][c], s);
        for (int r = 0; r < 4; r++) {
            if (r == col) continue;
            float f = m[r][col];
            for (int c = 0; c < 8; c++) m[r][c] = __fmaf_rn(-f, m[col][c], m[r][c]);
        }
    }
    for (int r = 0; r < 4; r++)
        for (int c = 0; c < 4; c++) o[r * 4 + c] = m[r][4 + c];
}

__global__ void build_mats_kernel(const float* __restrict__ K,
                                  const float* __restrict__ srcRTinv,
                                  const float* __restrict__ dstRT) {
    int bv = threadIdx.x;
    if (bv >= BV) return;
    int b = bv / Vv;
    float Kb[16], Ki[16];
    for (int i = 0; i < 16; i++) Kb[i] = K[b * 16 + i];
    inv4(Kb, Ki);
    float* out = &g_mats[bv * 64];
    for (int i = 0; i < 16; i++) {
        out[i]      = Ki[i];
        out[16 + i] = srcRTinv[bv * 16 + i];
        out[32 + i] = dstRT[b * 16 + i];   // dst_RTs is (B,1,4,4)
        out[48 + i] = Kb[i];
    }
}

// ---------------- projection precompute (1 thread / pixel) + zero g_wz -----------
__global__ void __launch_bounds__(256) proj_kernel(const float* __restrict__ depths) {
    int w = blockIdx.x * blockDim.x + threadIdx.x;   // BV*Nn threads
    // fused: zero wz (one float2 per thread)
    reinterpret_cast<float2*>(g_wz)[w] = make_float2(0.f, 0.f);

    int bv = w >> 16;
    int n = w & (Nn - 1);
    float gx = (float)(n & (Ww - 1));
    float gy = (float)(n >> 8);

    float d = __ldg(&depths[w]);
    const float* M = &g_mats[bv * 64];

    // Exact fp32 reference chain: xyp = K*(dstRT*(srcRTinv*(Kinv*proj)))
    float pr[4] = {__fmul_rn(gx, d), __fmul_rn(gy, d), d, 1.f};
    float cam[4], wld[4], c2[4], xyp[4];
    mv4((const float4*)(M + 0),  pr,  cam);
    mv4((const float4*)(M + 16), cam, wld);
    mv4((const float4*)(M + 32), wld, c2);
    mv4((const float4*)(M + 48), c2,  xyp);

    float Z = xyp[2];
    float zeps = __fadd_rn(Z, EPSF);
    float x = __fdiv_rn(xyp[0], zeps);     // reference: xyp0 / (z + eps)
    float y = __fdiv_rn(xyp[1], zeps);
    float invz = __frcp_rn(zeps);          // reference: 1.0 / (z + eps)
    g_xyz[w] = make_float4(x, y, invz, Z);
}

// ---------------- transpose feats (BV,C,N) -> (BV,N,C), fused zero of g_acc ------
__global__ void transpose_kernel(const float* __restrict__ in) {
    __shared__ float tile[32][33];
    int bv = blockIdx.z;
    int c0 = blockIdx.y * 32;
    int n0 = blockIdx.x * 32;
    const float* ip = in + (size_t)bv * Cc * Nn;
    float* op = g_featsT + (size_t)bv * Nn * Cc;
    int tx = threadIdx.x, ty = threadIdx.y;

    // fused: zero acc (1 float4 per thread; 32768 blocks x 256 threads == 8M float4)
    size_t zid = ((size_t)((blockIdx.z * gridDim.y + blockIdx.y) * gridDim.x + blockIdx.x)) * 256
                 + ty * 32 + tx;
    reinterpret_cast<float4*>(g_acc)[zid] = make_float4(0.f, 0.f, 0.f, 0.f);

#pragma unroll
    for (int i = 0; i < 32; i += 8)
        tile[ty + i][tx] = ip[(size_t)(c0 + ty + i) * Nn + n0 + tx];
    __syncthreads();
#pragma unroll
    for (int i = 0; i < 32; i += 8)
        op[(size_t)(n0 + ty + i) * Cc + c0 + tx] = tile[tx][ty + i];
}

// ---------------- phase A: feature acc taps (templated on bounds checking) -------
template <bool CHECK>
__device__ __forceinline__ void do_taps(float fx, float fy, float invz,
                                        float* accp, float4 f,
                                        bool hb, float px0, float py0) {
    float nhiz = __fmul_rn(invz, -0.5f);   // exact
#pragma unroll
    for (int i = 0; i < 11; i++) {
        float dxf = hb ? TDX[2 * i + 1] : TDX[2 * i];
        float dyf = hb ? TDY[2 * i + 1] : TDY[2 * i];
        int off   = hb ? TOFF[2 * i + 1] : TOFF[2 * i];
        float ddx = dxf + fx;
        float ddy = dyf + fy;
        float s2 = __fmaf_rn(ddx, ddx, __fmaf_rn(ddy, ddy, EPSF));
        float dist;
        asm("sqrt.approx.f32 %0, %1;" : "=f"(dist) : "f"(s2));
        // ws = (1 - dist/2) * invz, fused; sign(ws) == sign(1 - dist/2) since invz>0
        float ws = __fmaf_rn(dist, nhiz, invz);
        bool live = ws > 0.f;
        if (CHECK) {
            float px = px0 + dxf;
            float py = py0 + dyf;
            live = live && (px >= 0.f) && (px < (float)Ww) &&
                           (py >= 0.f) && (py < (float)Hh);
        }
        if (live) {
            float* p = accp + ((long)off << 6);
            asm volatile("red.global.add.v4.f32 [%0], {%1,%2,%3,%4};" ::
                         "l"(p), "f"(__fmul_rn(ws, f.x)), "f"(__fmul_rn(ws, f.y)),
                         "f"(__fmul_rn(ws, f.z)), "f"(__fmul_rn(ws, f.w)) : "memory");
        }
    }
}

// ---------------- splat: one warp per source pixel ------------------------------
__global__ void __launch_bounds__(256, 8) splat_kernel() {
    int w = (int)((blockIdx.x * blockDim.x + threadIdx.x) >> 5);
    int lane = threadIdx.x & 31;
    int bv = w >> 16;            // N = 65536

    float4 pj = __ldg(&g_xyz[w]);    // {x, y, invz, Z} — warp-uniform broadcast
    float Z = pj.w;
    if (!(Z > EPSF)) return;         // warp-uniform; ref adds w=0 -> no-op
    float x = pj.x, y = pj.y, invz = pj.z;
    float px0 = rintf(x);            // matches jnp.round (half-to-even)
    float py0 = rintf(y);

    float fx = px0 - x;              // feeds approx dist only
    float fy = py0 - y;
    int ix0 = (int)px0;              // exact: px0 integral
    int iy0 = (int)py0;
    long idx_base = (long)iy0 * Ww + ix0;

    float* wzp = g_wz + (((long)bv << 17) + (idx_base << 1));
    float nhiz = __fmul_rn(invz, -0.5f);
    bool interior = (px0 >= 2.f) && (px0 <= (float)(Ww - 3)) &&
                    (py0 >= 2.f) && (py0 <= (float)(Hh - 3));

    // ---- phase B: one warp-wide v2 RED covers all 21 taps' (w, w*z).
    // Taps are row-major -> addresses form 5 contiguous runs -> HW coalesces
    // each run into ~1 L1 wavefront (vs 1 per tap before).
    if (lane < 21) {
        float dxf = LDXt[lane];
        float dyf = LDYt[lane];
        int  offt = LOFFt[lane];
        float ddx = dxf + fx;
        float ddy = dyf + fy;
        float s2 = __fmaf_rn(ddx, ddx, __fmaf_rn(ddy, ddy, EPSF));
        float dist;
        asm("sqrt.approx.f32 %0, %1;" : "=f"(dist) : "f"(s2));
        float ws = __fmaf_rn(dist, nhiz, invz);   // identical value to phase A
        bool live = ws > 0.f;
        if (!interior) {
            float px = px0 + dxf;
            float py = py0 + dyf;
            live = live && (px >= 0.f) && (px < (float)Ww) &&
                           (py >= 0.f) && (py < (float)Hh);
        }
        if (live) {
            float* q = wzp + ((long)offt << 1);
            asm volatile("red.global.add.v2.f32 [%0], {%1,%2};" ::
                         "l"(q), "f"(ws), "f"(__fmul_rn(ws, Z)) : "memory");
        }
    }

    // ---- phase A: feature accumulation (half-warp per tap, v4 per lane).
    bool hb = lane >= 16;        // half-warp id: tap parity
    int sl = lane & 15;          // sub-lane: channel group
    float4 f = *reinterpret_cast<const float4*>(&g_featsT[((size_t)w << 6) + 4 * sl]);
    float* accp = g_acc + (((long)bv << 22) + (idx_base << 6) + 4 * sl);

    if (interior)
        do_taps<false>(fx, fy, invz, accp, f, hb, px0, py0);
    else
        do_taps<true>(fx, fy, invz, accp, f, hb, px0, py0);
}

// ---------------- normalize + transpose back to (BV, C+1, N) --------------------
__global__ void __launch_bounds__(256) normalize_kernel(float* __restrict__ out) {
    __shared__ float tile[64][33];
    __shared__ float ws[32];
    __shared__ float zs[32];
    int bv = blockIdx.y;
    int n0 = blockIdx.x * 32;
    int tid = threadIdx.x;

    const float* acc = g_acc + (((size_t)bv * Nn + n0) << 6);
    for (int l = tid; l < 32 * 64; l += 256) {
        int p = l >> 6;
        int c = l & 63;
        tile[c][p] = acc[l];   // acc[p*64+c] == acc[l]
    }
    if (tid < 32) {
        float2 wzv = *reinterpret_cast<const float2*>(&g_wz[((size_t)(bv * Nn + n0 + tid)) << 1]);
        ws[tid] = __fadd_rn(wzv.x, EPSF);
        zs[tid] = wzv.y;
    }
    __syncthreads();

    float* ob = out + (size_t)bv * (Cc + 1) * Nn + n0;
    for (int l = tid; l < 32 * 64; l += 256) {
        int c = l >> 5;
        int p = l & 31;
        ob[(size_t)c * Nn + p] = __fdiv_rn(tile[c][p], ws[p]);
    }
    if (tid < 32) ob[(size_t)Cc * Nn + tid] = __fdiv_rn(zs[tid], ws[tid]);
}

// ---------------- launch ---------------------------------------------------------
extern "C" void kernel_launch(void* const* d_in, const int* in_sizes, int n_in,
                              void* d_out, int out_size) {
    const float* feats    = (const float*)d_in[0];
    const float* depths   = (const float*)d_in[1];
    const float* K        = (const float*)d_in[2];
    const float* srcRTinv = (const float*)d_in[4];
    const float* dstRT    = (const float*)d_in[5];
    float* out = (float*)d_out;

    build_mats_kernel<<<1, 32>>>(K, srcRTinv, dstRT);
    proj_kernel<<<(BV * Nn) / 256, 256>>>(depths);                       // + zeroes g_wz
    transpose_kernel<<<dim3(Nn / 32, Cc / 32, BV), dim3(32, 8)>>>(feats); // + zeroes g_acc
    splat_kernel<<<(BV * Nn * 32) / 256, 256>>>();
    normalize_kernel<<<dim3(Nn / 32, BV), 256>>>(out);
}

// round 8
// speedup vs baseline: 1.5377x; 1.1243x over previous
#include <cuda_runtime.h>
#include <cstdint>

#define Bb 2
#define Vv 4
#define Cc 64
#define Hh 256
#define Ww 256
#define Nn (Hh * Ww)       // 65536
#define BV (Bb * Vv)       // 8
#define EPSF 1e-8f

// ---------------- scratch (device globals: allocation-free per harness rules) ----
__device__ float g_featsT[(size_t)BV * Nn * Cc];  // feats transposed to (BV, N, C)  128MB
__device__ float g_acc[(size_t)BV * Nn * Cc];     // accumulator (BV, N, C)          128MB
__device__ float g_wz[(size_t)BV * Nn * 2];       // per-target (wsum, wz)             4MB
__device__ float4 g_xyz[(size_t)BV * Nn];         // per-pixel {x, y, invz, Z}         8MB
// per-bv matrices (exact fp32): [Kinv(16), srcRTinv(16), dstRT(16), K(16)]
__device__ float g_mats[BV * 64];

// Exact fp32 4x4 matvec, fma chain ascending j (matches XLA dot lowering order).
__device__ __forceinline__ void mv4(const float4* __restrict__ M,
                                    const float v[4], float o[4]) {
#pragma unroll
    for (int r = 0; r < 4; r++) {
        float4 m = __ldg(&M[r]);
        float s = __fmul_rn(m.x, v[0]);
        s = __fmaf_rn(m.y, v[1], s);
        s = __fmaf_rn(m.z, v[2], s);
        s = __fmaf_rn(m.w, v[3], s);
        o[r] = s;
    }
}

// ---------------- 4x4 inverse (Gauss-Jordan, partial pivot) ---------------------
__device__ void inv4(const float* a, float* o) {
    float m[4][8];
    for (int r = 0; r < 4; r++)
        for (int c = 0; c < 4; c++) {
            m[r][c] = a[r * 4 + c];
            m[r][4 + c] = (r == c) ? 1.f : 0.f;
        }
    for (int col = 0; col < 4; col++) {
        int piv = col;
        for (int r = col + 1; r < 4; r++)
            if (fabsf(m[r][col]) > fabsf(m[piv][col])) piv = r;
        if (piv != col)
            for (int c = 0; c < 8; c++) { float t = m[col][c]; m[col][c] = m[piv][c]; m[piv][c] = t; }
        float s = __fdiv_rn(1.f, m[col][col]);
        for (int c = 0; c < 8; c++) m[col][c] = __fmul_rn(m[col][c], s);
        for (int r = 0; r < 4; r++) {
            if (r == col) continue;
            float f = m[r][col];
            for (int c = 0; c < 8; c++) m[r][c] = __fmaf_rn(-f, m[col][c], m[r][c]);
        }
    }
    for (int r = 0; r < 4; r++)
        for (int c = 0; c < 4; c++) o[r * 4 + c] = m[r][4 + c];
}

__global__ void build_mats_kernel(const float* __restrict__ K,
                                  const float* __restrict__ srcRTinv,
                                  const float* __restrict__ dstRT) {
    int bv = threadIdx.x;
    if (bv >= BV) return;
    int b = bv / Vv;
    float Kb[16], Ki[16];
    for (int i = 0; i < 16; i++) Kb[i] = K[b * 16 + i];
    inv4(Kb, Ki);
    float* out = &g_mats[bv * 64];
    for (int i = 0; i < 16; i++) {
        out[i]      = Ki[i];
        out[16 + i] = srcRTinv[bv * 16 + i];
        out[32 + i] = dstRT[b * 16 + i];   // dst_RTs is (B,1,4,4)
        out[48 + i] = Kb[i];
    }
}

// ---------------- projection precompute (1 thread / pixel) + zero g_wz -----------
__global__ void __launch_bounds__(256) proj_kernel(const float* __restrict__ depths) {
    int w = blockIdx.x * blockDim.x + threadIdx.x;   // BV*Nn threads
    // fused: zero wz (one float2 per thread)
    reinterpret_cast<float2*>(g_wz)[w] = make_float2(0.f, 0.f);

    int bv = w >> 16;
    int n = w & (Nn - 1);
    float gx = (float)(n & (Ww - 1));
    float gy = (float)(n >> 8);

    float d = __ldg(&depths[w]);
    const float* M = &g_mats[bv * 64];

    // Exact fp32 reference chain: xyp = K*(dstRT*(srcRTinv*(Kinv*proj)))
    float pr[4] = {__fmul_rn(gx, d), __fmul_rn(gy, d), d, 1.f};
    float cam[4], wld[4], c2[4], xyp[4];
    mv4((const float4*)(M + 0),  pr,  cam);
    mv4((const float4*)(M + 16), cam, wld);
    mv4((const float4*)(M + 32), wld, c2);
    mv4((const float4*)(M + 48), c2,  xyp);

    float Z = xyp[2];
    float zeps = __fadd_rn(Z, EPSF);
    float x = __fdiv_rn(xyp[0], zeps);     // reference: xyp0 / (z + eps)
    float y = __fdiv_rn(xyp[1], zeps);
    float invz = __frcp_rn(zeps);          // reference: 1.0 / (z + eps)
    g_xyz[w] = make_float4(x, y, invz, Z);
}

// ---------------- transpose feats (BV,C,N) -> (BV,N,C), fused zero of g_acc ------
__global__ void transpose_kernel(const float* __restrict__ in) {
    __shared__ float tile[32][33];
    int bv = blockIdx.z;
    int c0 = blockIdx.y * 32;
    int n0 = blockIdx.x * 32;
    const float* ip = in + (size_t)bv * Cc * Nn;
    float* op = g_featsT + (size_t)bv * Nn * Cc;
    int tx = threadIdx.x, ty = threadIdx.y;

    // fused: zero acc (1 float4 per thread; 32768 blocks x 256 threads == 8M float4)
    size_t zid = ((size_t)((blockIdx.z * gridDim.y + blockIdx.y) * gridDim.x + blockIdx.x)) * 256
                 + ty * 32 + tx;
    reinterpret_cast<float4*>(g_acc)[zid] = make_float4(0.f, 0.f, 0.f, 0.f);

#pragma unroll
    for (int i = 0; i < 32; i += 8)
        tile[ty + i][tx] = ip[(size_t)(c0 + ty + i) * Nn + n0 + tx];
    __syncthreads();
#pragma unroll
    for (int i = 0; i < 32; i += 8)
        op[(size_t)(n0 + ty + i) * Cc + c0 + tx] = tile[tx][ty + i];
}

// ---------------- phase A: quadrant-specialized 4x4 tap grid --------------------
// Quadrant (QX,QY): QX=1 means cx = x-px0 >= 0 -> dx in {-1,0,1,2} (dx=-2 column
// provably dead: s2 >= 4+eps -> w<0). Far corner of the 4x4 grid is always dead
// (min s2 = 4.5) and is auto-killed by the ws>0 predicate. 16 slots, 8 iters.
template <int QX, int QY, bool CHECK>
__device__ __forceinline__ void do_taps(float fx, float fy, float invz,
                                        float* accp, float4 f,
                                        int hb, float px0, float py0) {
    const float nhiz = __fmul_rn(invz, -0.5f);   // exact
    const int IDX0 = QX ? -1 : -2;
    const int IDY0 = QY ? -1 : -2;
    const float hbf = (float)hb;
#pragma unroll
    for (int i = 0; i < 8; i++) {
        const int jxb = (2 * i) & 3;             // compile-time
        const int jy  = i >> 1;                  // compile-time
        float dxf = (float)(jxb + IDX0) + hbf;   // const + hbf
        float dyf = (float)(jy + IDY0);          // immediate
        int off = (jy + IDY0) * 256 + jxb + IDX0 + hb;  // const + hb
        float ddx = dxf + fx;
        float ddy = dyf + fy;
        float s2 = __fmaf_rn(ddx, ddx, __fmaf_rn(ddy, ddy, EPSF));
        float dist;
        asm("sqrt.approx.f32 %0, %1;" : "=f"(dist) : "f"(s2));
        // ws = (1 - dist/2) * invz, fused; sign(ws) == sign(1 - dist/2) since invz>0
        float ws = __fmaf_rn(dist, nhiz, invz);
        bool live = ws > 0.f;
        if (CHECK) {
            float px = px0 + dxf;
            float py = py0 + dyf;
            live = live && (px >= 0.f) && (px < (float)Ww) &&
                           (py >= 0.f) && (py < (float)Hh);
        }
        if (live) {
            float* p = accp + ((long)off << 6);
            asm volatile("red.global.add.v4.f32 [%0], {%1,%2,%3,%4};" ::
                         "l"(p), "f"(__fmul_rn(ws, f.x)), "f"(__fmul_rn(ws, f.y)),
                         "f"(__fmul_rn(ws, f.z)), "f"(__fmul_rn(ws, f.w)) : "memory");
        }
    }
}

// ---------------- splat: one warp per source pixel ------------------------------
__global__ void __launch_bounds__(256, 8) splat_kernel() {
    int w = (int)((blockIdx.x * blockDim.x + threadIdx.x) >> 5);
    int lane = threadIdx.x & 31;
    int bv = w >> 16;            // N = 65536

    float4 pj = __ldg(&g_xyz[w]);    // {x, y, invz, Z} — warp-uniform broadcast
    float Z = pj.w;
    if (!(Z > EPSF)) return;         // warp-uniform; ref adds w=0 -> no-op
    float x = pj.x, y = pj.y, invz = pj.z;
    float px0 = rintf(x);            // matches jnp.round (half-to-even)
    float py0 = rintf(y);

    float fx = px0 - x;              // feeds approx dist only
    float fy = py0 - y;
    int ix0 = (int)px0;              // exact: px0 integral
    int iy0 = (int)py0;
    long idx_base = (long)iy0 * Ww + ix0;

    bool qx = (fx <= 0.f);           // cx >= 0
    bool qy = (fy <= 0.f);
    float nhiz = __fmul_rn(invz, -0.5f);
    bool interior = (px0 >= 2.f) && (px0 <= (float)(Ww - 3)) &&
                    (py0 >= 2.f) && (py0 <= (float)(Hh - 3));

    // ---- phase B: one warp-wide v2 RED covers the 16-slot quadrant grid's (w, w*z).
    if (lane < 16) {
        int iqx0 = qx ? -1 : -2;
        int iqy0 = qy ? -1 : -2;
        int jx = lane & 3, jy = lane >> 2;
        float dxf = (float)(jx + iqx0);
        float dyf = (float)(jy + iqy0);
        int offt = (jy + iqy0) * 256 + jx + iqx0;
        float ddx = dxf + fx;
        float ddy = dyf + fy;
        float s2 = __fmaf_rn(ddx, ddx, __fmaf_rn(ddy, ddy, EPSF));
        float dist;
        asm("sqrt.approx.f32 %0, %1;" : "=f"(dist) : "f"(s2));
        float ws = __fmaf_rn(dist, nhiz, invz);   // identical value to phase A
        bool live = ws > 0.f;
        if (!interior) {
            float px = px0 + dxf;
            float py = py0 + dyf;
            live = live && (px >= 0.f) && (px < (float)Ww) &&
                           (py >= 0.f) && (py < (float)Hh);
        }
        if (live) {
            float* q = g_wz + (((long)bv << 17) + ((idx_base + offt) << 1));
            asm volatile("red.global.add.v2.f32 [%0], {%1,%2};" ::
                         "l"(q), "f"(ws), "f"(__fmul_rn(ws, Z)) : "memory");
        }
    }

    // ---- phase A: feature accumulation (half-warp per tap, v4 per lane).
    int hb = lane >> 4;          // half-warp id: tap parity
    int sl = lane & 15;          // sub-lane: channel group
    float4 f = *reinterpret_cast<const float4*>(&g_featsT[((size_t)w << 6) + 4 * sl]);
    float* accp = g_acc + (((long)bv << 22) + (idx_base << 6) + 4 * sl);

    if (interior) {
        if (qx) { if (qy) do_taps<1,1,false>(fx,fy,invz,accp,f,hb,px0,py0);
                  else    do_taps<1,0,false>(fx,fy,invz,accp,f,hb,px0,py0); }
        else    { if (qy) do_taps<0,1,false>(fx,fy,invz,accp,f,hb,px0,py0);
                  else    do_taps<0,0,false>(fx,fy,invz,accp,f,hb,px0,py0); }
    } else {
        if (qx) { if (qy) do_taps<1,1,true>(fx,fy,invz,accp,f,hb,px0,py0);
                  else    do_taps<1,0,true>(fx,fy,invz,accp,f,hb,px0,py0); }
        else    { if (qy) do_taps<0,1,true>(fx,fy,invz,accp,f,hb,px0,py0);
                  else    do_taps<0,0,true>(fx,fy,invz,accp,f,hb,px0,py0); }
    }
}

// ---------------- normalize: 64-px tiles, rcp+mul, float4 I/O -------------------
__global__ void __launch_bounds__(256) normalize_kernel(float* __restrict__ out) {
    __shared__ float tile[64][65];   // [channel][pixel]
    __shared__ float rws[64];
    __shared__ float zss[64];
    int bv = blockIdx.y;
    int n0 = blockIdx.x * 64;
    int tid = threadIdx.x;

    const float4* acc4 = reinterpret_cast<const float4*>(g_acc + (((size_t)bv * Nn + n0) << 6));
#pragma unroll
    for (int r = 0; r < 4; r++) {
        int idx = r * 256 + tid;     // [0, 1024)
        int p = idx >> 4;            // pixel 0..63
        int cq = idx & 15;           // channel quad
        float4 v = acc4[idx];
        tile[4 * cq + 0][p] = v.x;
        tile[4 * cq + 1][p] = v.y;
        tile[4 * cq + 2][p] = v.z;
        tile[4 * cq + 3][p] = v.w;
    }
    if (tid < 64) {
        float2 wzv = reinterpret_cast<const float2*>(g_wz)[(size_t)bv * Nn + n0 + tid];
        rws[tid] = __frcp_rn(__fadd_rn(wzv.x, EPSF));  // rcp+mul vs div: <=2ulp
        zss[tid] = wzv.y;
    }
    __syncthreads();

    float* ob = out + (size_t)bv * (Cc + 1) * Nn + n0;
#pragma unroll
    for (int r = 0; r < 4; r++) {
        int idx = r * 256 + tid;
        int c = idx >> 4;            // channel 0..63
        int j = idx & 15;            // pixel quad
        float4 o;
        o.x = __fmul_rn(tile[c][4 * j + 0], rws[4 * j + 0]);
        o.y = __fmul_rn(tile[c][4 * j + 1], rws[4 * j + 1]);
        o.z = __fmul_rn(tile[c][4 * j + 2], rws[4 * j + 2]);
        o.w = __fmul_rn(tile[c][4 * j + 3], rws[4 * j + 3]);
        reinterpret_cast<float4*>(ob + (size_t)c * Nn)[j] = o;
    }
    if (tid < 16) {
        int j = tid;
        float4 o;
        o.x = __fmul_rn(zss[4 * j + 0], rws[4 * j + 0]);
        o.y = __fmul_rn(zss[4 * j + 1], rws[4 * j + 1]);
        o.z = __fmul_rn(zss[4 * j + 2], rws[4 * j + 2]);
        o.w = __fmul_rn(zss[4 * j + 3], rws[4 * j + 3]);
        reinterpret_cast<float4*>(ob + (size_t)Cc * Nn)[j] = o;
    }
}

// ---------------- launch ---------------------------------------------------------
extern "C" void kernel_launch(void* const* d_in, const int* in_sizes, int n_in,
                              void* d_out, int out_size) {
    const float* feats    = (const float*)d_in[0];
    const float* depths   = (const float*)d_in[1];
    const float* K        = (const float*)d_in[2];
    const float* srcRTinv = (const float*)d_in[4];
    const float* dstRT    = (const float*)d_in[5];
    float* out = (float*)d_out;

    build_mats_kernel<<<1, 32>>>(K, srcRTinv, dstRT);
    proj_kernel<<<(BV * Nn) / 256, 256>>>(depths);                       // + zeroes g_wz
    transpose_kernel<<<dim3(Nn / 32, Cc / 32, BV), dim3(32, 8)>>>(feats); // + zeroes g_acc
    splat_kernel<<<(BV * Nn * 32) / 256, 256>>>();
    normalize_kernel<<<dim3(Nn / 64, BV), 256>>>(out);
}

// round 9
// speedup vs baseline: 1.5493x; 1.0076x over previous
#include <cuda_runtime.h>
#include <cstdint>

#define Bb 2
#define Vv 4
#define Cc 64
#define Hh 256
#define Ww 256
#define Nn (Hh * Ww)       // 65536
#define BV (Bb * Vv)       // 8
#define EPSF 1e-8f

// ---------------- scratch (device globals: allocation-free per harness rules) ----
__device__ float g_featsT[(size_t)BV * Nn * Cc];  // feats transposed to (BV, N, C)  128MB
__device__ float g_acc[(size_t)BV * Nn * Cc];     // accumulator (BV, N, C)          128MB
__device__ float g_wz[(size_t)BV * Nn * 2];       // per-target (wsum, wz)             4MB
__device__ float4 g_xyz[(size_t)BV * Nn];         // per-pixel {x, y, invz, Z}         8MB
// per-bv matrices (exact fp32): [Kinv(16), srcRTinv(16), dstRT(16), K(16)]
__device__ float g_mats[BV * 64];

// ---------------- streams/events for fork-join overlap (created at load time, ---
// ---------------- before any harness mem checkpoint; no device allocations) ------
namespace {
struct StreamCtx {
    cudaStream_t s[2];
    cudaEvent_t fork;
    cudaEvent_t join[2];
    StreamCtx() {
        cudaStreamCreateWithFlags(&s[0], cudaStreamNonBlocking);
        cudaStreamCreateWithFlags(&s[1], cudaStreamNonBlocking);
        cudaEventCreateWithFlags(&fork, cudaEventDisableTiming);
        cudaEventCreateWithFlags(&join[0], cudaEventDisableTiming);
        cudaEventCreateWithFlags(&join[1], cudaEventDisableTiming);
    }
};
StreamCtx g_sc;
}

// Exact fp32 4x4 matvec, fma chain ascending j (matches XLA dot lowering order).
__device__ __forceinline__ void mv4(const float4* __restrict__ M,
                                    const float v[4], float o[4]) {
#pragma unroll
    for (int r = 0; r < 4; r++) {
        float4 m = __ldg(&M[r]);
        float s = __fmul_rn(m.x, v[0]);
        s = __fmaf_rn(m.y, v[1], s);
        s = __fmaf_rn(m.z, v[2], s);
        s = __fmaf_rn(m.w, v[3], s);
        o[r] = s;
    }
}

// ---------------- 4x4 inverse (Gauss-Jordan, partial pivot) ---------------------
__device__ void inv4(const float* a, float* o) {
    float m[4][8];
    for (int r = 0; r < 4; r++)
        for (int c = 0; c < 4; c++) {
            m[r][c] = a[r * 4 + c];
            m[r][4 + c] = (r == c) ? 1.f : 0.f;
        }
    for (int col = 0; col < 4; col++) {
        int piv = col;
        for (int r = col + 1; r < 4; r++)
            if (fabsf(m[r][col]) > fabsf(m[piv][col])) piv = r;
        if (piv != col)
            for (int c = 0; c < 8; c++) { float t = m[col][c]; m[col][c] = m[piv][c]; m[piv][c] = t; }
        float s = __fdiv_rn(1.f, m[col][col]);
        for (int c = 0; c < 8; c++) m[col][c] = __fmul_rn(m[col][c], s);
        for (int r = 0; r < 4; r++) {
            if (r == col) continue;
            float f = m[r][col];
            for (int c = 0; c < 8; c++) m[r][c] = __fmaf_rn(-f, m[col][c], m[r][c]);
        }
    }
    for (int r = 0; r < 4; r++)
        for (int c = 0; c < 4; c++) o[r * 4 + c] = m[r][4 + c];
}

__global__ void build_mats_kernel(const float* __restrict__ K,
                                  const float* __restrict__ srcRTinv,
                                  const float* __restrict__ dstRT) {
    int bv = threadIdx.x;
    if (bv >= BV) return;
    int b = bv / Vv;
    float Kb[16], Ki[16];
    for (int i = 0; i < 16; i++) Kb[i] = K[b * 16 + i];
    inv4(Kb, Ki);
    float* out = &g_mats[bv * 64];
    for (int i = 0; i < 16; i++) {
        out[i]      = Ki[i];
        out[16 + i] = srcRTinv[bv * 16 + i];
        out[32 + i] = dstRT[b * 16 + i];   // dst_RTs is (B,1,4,4)
        out[48 + i] = Kb[i];
    }
}

// ---------------- projection precompute (1 thread / pixel) + zero g_wz, per bv ---
__global__ void __launch_bounds__(256) proj_kernel(const float* __restrict__ depths, int bv) {
    int n = blockIdx.x * blockDim.x + threadIdx.x;   // Nn threads per slice
    int w = (bv << 16) + n;
    // fused: zero wz (one float2 per thread)
    reinterpret_cast<float2*>(g_wz)[w] = make_float2(0.f, 0.f);

    float gx = (float)(n & (Ww - 1));
    float gy = (float)(n >> 8);

    float d = __ldg(&depths[w]);
    const float* M = &g_mats[bv * 64];

    // Exact fp32 reference chain: xyp = K*(dstRT*(srcRTinv*(Kinv*proj)))
    float pr[4] = {__fmul_rn(gx, d), __fmul_rn(gy, d), d, 1.f};
    float cam[4], wld[4], c2[4], xyp[4];
    mv4((const float4*)(M + 0),  pr,  cam);
    mv4((const float4*)(M + 16), cam, wld);
    mv4((const float4*)(M + 32), wld, c2);
    mv4((const float4*)(M + 48), c2,  xyp);

    float Z = xyp[2];
    float zeps = __fadd_rn(Z, EPSF);
    float x = __fdiv_rn(xyp[0], zeps);     // reference: xyp0 / (z + eps)
    float y = __fdiv_rn(xyp[1], zeps);
    float invz = __frcp_rn(zeps);          // reference: 1.0 / (z + eps)
    g_xyz[w] = make_float4(x, y, invz, Z);
}

// ---------------- transpose feats (C,N)->(N,C) for one bv, fused zero of g_acc ---
__global__ void transpose_kernel(const float* __restrict__ in, int bv) {
    __shared__ float tile[32][33];
    int c0 = blockIdx.y * 32;
    int n0 = blockIdx.x * 32;
    const float* ip = in + (size_t)bv * Cc * Nn;
    float* op = g_featsT + (size_t)bv * Nn * Cc;
    int tx = threadIdx.x, ty = threadIdx.y;

    // fused: zero this bv's acc slice (4096 blocks x 256 thr = 1M float4 = 16MB)
    size_t zid = ((size_t)(blockIdx.y * gridDim.x + blockIdx.x)) * 256 + ty * 32 + tx;
    reinterpret_cast<float4*>(g_acc + (size_t)bv * Nn * Cc)[zid] =
        make_float4(0.f, 0.f, 0.f, 0.f);

#pragma unroll
    for (int i = 0; i < 32; i += 8)
        tile[ty + i][tx] = ip[(size_t)(c0 + ty + i) * Nn + n0 + tx];
    __syncthreads();
#pragma unroll
    for (int i = 0; i < 32; i += 8)
        op[(size_t)(n0 + ty + i) * Cc + c0 + tx] = tile[tx][ty + i];
}

// ---------------- phase A: quadrant-specialized 4x4 tap grid --------------------
// Quadrant (QX,QY): QX=1 means cx = x-px0 >= 0 -> dx in {-1,0,1,2} (dx=-2 column
// provably dead: s2 >= 4+eps -> w<0). Far corner of the 4x4 grid is always dead
// (min s2 = 4.5) and is auto-killed by the ws>0 predicate. 16 slots, 8 iters.
template <int QX, int QY, bool CHECK>
__device__ __forceinline__ void do_taps(float fx, float fy, float invz,
                                        float* accp, float4 f,
                                        int hb, float px0, float py0) {
    const float nhiz = __fmul_rn(invz, -0.5f);   // exact
    const int IDX0 = QX ? -1 : -2;
    const int IDY0 = QY ? -1 : -2;
    const float hbf = (float)hb;
#pragma unroll
    for (int i = 0; i < 8; i++) {
        const int jxb = (2 * i) & 3;             // compile-time
        const int jy  = i >> 1;                  // compile-time
        float dxf = (float)(jxb + IDX0) + hbf;   // const + hbf
        float dyf = (float)(jy + IDY0);          // immediate
        int off = (jy + IDY0) * 256 + jxb + IDX0 + hb;  // const + hb
        float ddx = dxf + fx;
        float ddy = dyf + fy;
        float s2 = __fmaf_rn(ddx, ddx, __fmaf_rn(ddy, ddy, EPSF));
        float dist;
        asm("sqrt.approx.f32 %0, %1;" : "=f"(dist) : "f"(s2));
        // ws = (1 - dist/2) * invz, fused; sign(ws) == sign(1 - dist/2) since invz>0
        float ws = __fmaf_rn(dist, nhiz, invz);
        bool live = ws > 0.f;
        if (CHECK) {
            float px = px0 + dxf;
            float py = py0 + dyf;
            live = live && (px >= 0.f) && (px < (float)Ww) &&
                           (py >= 0.f) && (py < (float)Hh);
        }
        if (live) {
            float* p = accp + ((long)off << 6);
            asm volatile("red.global.add.v4.f32 [%0], {%1,%2,%3,%4};" ::
                         "l"(p), "f"(__fmul_rn(ws, f.x)), "f"(__fmul_rn(ws, f.y)),
                         "f"(__fmul_rn(ws, f.z)), "f"(__fmul_rn(ws, f.w)) : "memory");
        }
    }
}

// ---------------- splat: one warp per source pixel, one bv per launch ------------
__global__ void __launch_bounds__(256, 8) splat_kernel(int bv) {
    int w = (bv << 16) + (int)((blockIdx.x * blockDim.x + threadIdx.x) >> 5);
    int lane = threadIdx.x & 31;

    float4 pj = __ldg(&g_xyz[w]);    // {x, y, invz, Z} — warp-uniform broadcast
    float Z = pj.w;
    if (!(Z > EPSF)) return;         // warp-uniform; ref adds w=0 -> no-op
    float x = pj.x, y = pj.y, invz = pj.z;
    float px0 = rintf(x);            // matches jnp.round (half-to-even)
    float py0 = rintf(y);

    float fx = px0 - x;              // feeds approx dist only
    float fy = py0 - y;
    int ix0 = (int)px0;              // exact: px0 integral
    int iy0 = (int)py0;
    long idx_base = (long)iy0 * Ww + ix0;

    bool qx = (fx <= 0.f);           // cx >= 0
    bool qy = (fy <= 0.f);
    float nhiz = __fmul_rn(invz, -0.5f);
    bool interior = (px0 >= 2.f) && (px0 <= (float)(Ww - 3)) &&
                    (py0 >= 2.f) && (py0 <= (float)(Hh - 3));

    // ---- phase B: one warp-wide v2 RED covers the 16-slot quadrant grid's (w, w*z).
    if (lane < 16) {
        int iqx0 = qx ? -1 : -2;
        int iqy0 = qy ? -1 : -2;
        int jx = lane & 3, jy = lane >> 2;
        float dxf = (float)(jx + iqx0);
        float dyf = (float)(jy + iqy0);
        int offt = (jy + iqy0) * 256 + jx + iqx0;
        float ddx = dxf + fx;
        float ddy = dyf + fy;
        float s2 = __fmaf_rn(ddx, ddx, __fmaf_rn(ddy, ddy, EPSF));
        float dist;
        asm("sqrt.approx.f32 %0, %1;" : "=f"(dist) : "f"(s2));
        float ws = __fmaf_rn(dist, nhiz, invz);   // identical value to phase A
        bool live = ws > 0.f;
        if (!interior) {
            float px = px0 + dxf;
            float py = py0 + dyf;
            live = live && (px >= 0.f) && (px < (float)Ww) &&
                           (py >= 0.f) && (py < (float)Hh);
        }
        if (live) {
            float* q = g_wz + (((long)bv << 17) + ((idx_base + offt) << 1));
            asm volatile("red.global.add.v2.f32 [%0], {%1,%2};" ::
                         "l"(q), "f"(ws), "f"(__fmul_rn(ws, Z)) : "memory");
        }
    }

    // ---- phase A: feature accumulation (half-warp per tap, v4 per lane).
    int hb = lane >> 4;          // half-warp id: tap parity
    int sl = lane & 15;          // sub-lane: channel group
    float4 f = *reinterpret_cast<const float4*>(&g_featsT[((size_t)w << 6) + 4 * sl]);
    float* accp = g_acc + (((long)bv << 22) + (idx_base << 6) + 4 * sl);

    if (interior) {
        if (qx) { if (qy) do_taps<1,1,false>(fx,fy,invz,accp,f,hb,px0,py0);
                  else    do_taps<1,0,false>(fx,fy,invz,accp,f,hb,px0,py0); }
        else    { if (qy) do_taps<0,1,false>(fx,fy,invz,accp,f,hb,px0,py0);
                  else    do_taps<0,0,false>(fx,fy,invz,accp,f,hb,px0,py0); }
    } else {
        if (qx) { if (qy) do_taps<1,1,true>(fx,fy,invz,accp,f,hb,px0,py0);
                  else    do_taps<1,0,true>(fx,fy,invz,accp,f,hb,px0,py0); }
        else    { if (qy) do_taps<0,1,true>(fx,fy,invz,accp,f,hb,px0,py0);
                  else    do_taps<0,0,true>(fx,fy,invz,accp,f,hb,px0,py0); }
    }
}

// ---------------- normalize: 64-px tiles, rcp+mul, float4 I/O, one bv ------------
__global__ void __launch_bounds__(256) normalize_kernel(float* __restrict__ out, int bv) {
    __shared__ float tile[64][65];   // [channel][pixel]
    __shared__ float rws[64];
    __shared__ float zss[64];
    int n0 = blockIdx.x * 64;
    int tid = threadIdx.x;

    const float4* acc4 = reinterpret_cast<const float4*>(g_acc + (((size_t)bv * Nn + n0) << 6));
#pragma unroll
    for (int r = 0; r < 4; r++) {
        int idx = r * 256 + tid;     // [0, 1024)
        int p = idx >> 4;            // pixel 0..63
        int cq = idx & 15;           // channel quad
        float4 v = acc4[idx];
        tile[4 * cq + 0][p] = v.x;
        tile[4 * cq + 1][p] = v.y;
        tile[4 * cq + 2][p] = v.z;
        tile[4 * cq + 3][p] = v.w;
    }
    if (tid < 64) {
        float2 wzv = reinterpret_cast<const float2*>(g_wz)[(size_t)bv * Nn + n0 + tid];
        rws[tid] = __frcp_rn(__fadd_rn(wzv.x, EPSF));  // rcp+mul vs div: <=2ulp
        zss[tid] = wzv.y;
    }
    __syncthreads();

    float* ob = out + (size_t)bv * (Cc + 1) * Nn + n0;
#pragma unroll
    for (int r = 0; r < 4; r++) {
        int idx = r * 256 + tid;
        int c = idx >> 4;            // channel 0..63
        int j = idx & 15;            // pixel quad
        float4 o;
        o.x = __fmul_rn(tile[c][4 * j + 0], rws[4 * j + 0]);
        o.y = __fmul_rn(tile[c][4 * j + 1], rws[4 * j + 1]);
        o.z = __fmul_rn(tile[c][4 * j + 2], rws[4 * j + 2]);
        o.w = __fmul_rn(tile[c][4 * j + 3], rws[4 * j + 3]);
        reinterpret_cast<float4*>(ob + (size_t)c * Nn)[j] = o;
    }
    if (tid < 16) {
        int j = tid;
        float4 o;
        o.x = __fmul_rn(zss[4 * j + 0], rws[4 * j + 0]);
        o.y = __fmul_rn(zss[4 * j + 1], rws[4 * j + 1]);
        o.z = __fmul_rn(zss[4 * j + 2], rws[4 * j + 2]);
        o.w = __fmul_rn(zss[4 * j + 3], rws[4 * j + 3]);
        reinterpret_cast<float4*>(ob + (size_t)Cc * Nn)[j] = o;
    }
}

// ---------------- launch: fork-join 2-stream pipeline over bv slices --------------
extern "C" void kernel_launch(void* const* d_in, const int* in_sizes, int n_in,
                              void* d_out, int out_size) {
    const float* feats    = (const float*)d_in[0];
    const float* depths   = (const float*)d_in[1];
    const float* K        = (const float*)d_in[2];
    const float* srcRTinv = (const float*)d_in[4];
    const float* dstRT    = (const float*)d_in[5];
    float* out = (float*)d_out;

    // origin stream (legacy default = capture origin)
    build_mats_kernel<<<1, 32>>>(K, srcRTinv, dstRT);
    cudaEventRecord(g_sc.fork, 0);
    cudaStreamWaitEvent(g_sc.s[0], g_sc.fork, 0);
    cudaStreamWaitEvent(g_sc.s[1], g_sc.fork, 0);

    // two independent per-slice chains; DRAM-bound transpose/normalize of one
    // slice overlaps the L1/atomic-bound splat of the other.
    for (int b = 0; b < BV; b++) {
        cudaStream_t st = g_sc.s[b & 1];
        proj_kernel<<<Nn / 256, 256, 0, st>>>(depths, b);
        transpose_kernel<<<dim3(Nn / 32, Cc / 32), dim3(32, 8), 0, st>>>(feats, b);
        splat_kernel<<<(Nn * 32) / 256, 256, 0, st>>>(b);
        normalize_kernel<<<Nn / 64, 256, 0, st>>>(out, b);
    }

    cudaEventRecord(g_sc.join[0], g_sc.s[0]);
    cudaEventRecord(g_sc.join[1], g_sc.s[1]);
    cudaStreamWaitEvent(0, g_sc.join[0], 0);
    cudaStreamWaitEvent(0, g_sc.join[1], 0);
}

// round 10
// speedup vs baseline: 1.5702x; 1.0135x over previous
#include <cuda_runtime.h>
#include <cstdint>

#define Bb 2
#define Vv 4
#define Cc 64
#define Hh 256
#define Ww 256
#define Nn (Hh * Ww)       // 65536
#define BV (Bb * Vv)       // 8
#define EPSF 1e-8f
#define NSLICE 4
#define BVS (BV / NSLICE)  // 2 bv per slice

// ---------------- scratch (device globals: allocation-free per harness rules) ----
__device__ float g_acc[(size_t)BV * Nn * Cc];     // accumulator (BV, N, C)          128MB
__device__ float g_wz[(size_t)BV * Nn * 2];       // per-target (wsum, wz)             4MB
__device__ float4 g_xyz[(size_t)BV * Nn];         // per-pixel {x, y, invz, Z}         8MB
// per-bv matrices (exact fp32): [Kinv(16), srcRTinv(16), dstRT(16), K(16)]
__device__ float g_mats[BV * 64];

// ---------------- streams/events (created at load time; no device allocations) ---
namespace {
struct StreamCtx {
    cudaStream_t s[2];
    cudaEvent_t fork;
    cudaEvent_t esp[NSLICE];   // splat-chain events
    cudaEvent_t join[2];
    StreamCtx() {
        cudaStreamCreateWithFlags(&s[0], cudaStreamNonBlocking);
        cudaStreamCreateWithFlags(&s[1], cudaStreamNonBlocking);
        cudaEventCreateWithFlags(&fork, cudaEventDisableTiming);
        for (int i = 0; i < NSLICE; i++)
            cudaEventCreateWithFlags(&esp[i], cudaEventDisableTiming);
        cudaEventCreateWithFlags(&join[0], cudaEventDisableTiming);
        cudaEventCreateWithFlags(&join[1], cudaEventDisableTiming);
    }
};
StreamCtx g_sc;
}

// Exact fp32 4x4 matvec, fma chain ascending j (matches XLA dot lowering order).
__device__ __forceinline__ void mv4(const float4* __restrict__ M,
                                    const float v[4], float o[4]) {
#pragma unroll
    for (int r = 0; r < 4; r++) {
        float4 m = __ldg(&M[r]);
        float s = __fmul_rn(m.x, v[0]);
        s = __fmaf_rn(m.y, v[1], s);
        s = __fmaf_rn(m.z, v[2], s);
        s = __fmaf_rn(m.w, v[3], s);
        o[r] = s;
    }
}

// ---------------- 4x4 inverse (Gauss-Jordan, partial pivot) ---------------------
__device__ void inv4(const float* a, float* o) {
    float m[4][8];
    for (int r = 0; r < 4; r++)
        for (int c = 0; c < 4; c++) {
            m[r][c] = a[r * 4 + c];
            m[r][4 + c] = (r == c) ? 1.f : 0.f;
        }
    for (int col = 0; col < 4; col++) {
        int piv = col;
        for (int r = col + 1; r < 4; r++)
            if (fabsf(m[r][col]) > fabsf(m[piv][col])) piv = r;
        if (piv != col)
            for (int c = 0; c < 8; c++) { float t = m[col][c]; m[col][c] = m[piv][c]; m[piv][c] = t; }
        float s = __fdiv_rn(1.f, m[col][col]);
        for (int c = 0; c < 8; c++) m[col][c] = __fmul_rn(m[col][c], s);
        for (int r = 0; r < 4; r++) {
            if (r == col) continue;
            float f = m[r][col];
            for (int c = 0; c < 8; c++) m[r][c] = __fmaf_rn(-f, m[col][c], m[r][c]);
        }
    }
    for (int r = 0; r < 4; r++)
        for (int c = 0; c < 4; c++) o[r * 4 + c] = m[r][4 + c];
}

__global__ void build_mats_kernel(const float* __restrict__ K,
                                  const float* __restrict__ srcRTinv,
                                  const float* __restrict__ dstRT) {
    int bv = threadIdx.x;
    if (bv >= BV) return;
    int b = bv / Vv;
    float Kb[16], Ki[16];
    for (int i = 0; i < 16; i++) Kb[i] = K[b * 16 + i];
    inv4(Kb, Ki);
    float* out = &g_mats[bv * 64];
    for (int i = 0; i < 16; i++) {
        out[i]      = Ki[i];
        out[16 + i] = srcRTinv[bv * 16 + i];
        out[32 + i] = dstRT[b * 16 + i];   // dst_RTs is (B,1,4,4)
        out[48 + i] = Kb[i];
    }
}

// ------- projection precompute (1 thread / pixel) + zero g_wz + zero g_acc -------
__global__ void __launch_bounds__(256) proj_kernel(const float* __restrict__ depths, int bv0) {
    int g = blockIdx.x * blockDim.x + threadIdx.x;   // [0, BVS*Nn)
    int bv = bv0 + (g >> 16);
    int n = g & (Nn - 1);
    int w = (bv << 16) + n;

    // fused: zero wz (one float2 per thread)
    reinterpret_cast<float2*>(g_wz)[w] = make_float2(0.f, 0.f);
    // fused: zero this slice's acc (16 float4 per thread, coalesced)
    {
        float4* a4 = reinterpret_cast<float4*>(g_acc + (size_t)bv0 * Nn * Cc);
        const int stride = BVS * Nn;   // threads in slice
        float4 z = make_float4(0.f, 0.f, 0.f, 0.f);
#pragma unroll
        for (int k = 0; k < 16; k++) a4[(size_t)k * stride + g] = z;
    }

    float gx = (float)(n & (Ww - 1));
    float gy = (float)(n >> 8);

    float d = __ldg(&depths[w]);
    const float* M = &g_mats[bv * 64];

    // Exact fp32 reference chain: xyp = K*(dstRT*(srcRTinv*(Kinv*proj)))
    float pr[4] = {__fmul_rn(gx, d), __fmul_rn(gy, d), d, 1.f};
    float cam[4], wld[4], c2[4], xyp[4];
    mv4((const float4*)(M + 0),  pr,  cam);
    mv4((const float4*)(M + 16), cam, wld);
    mv4((const float4*)(M + 32), wld, c2);
    mv4((const float4*)(M + 48), c2,  xyp);

    float Z = xyp[2];
    float zeps = __fadd_rn(Z, EPSF);
    float x = __fdiv_rn(xyp[0], zeps);     // reference: xyp0 / (z + eps)
    float y = __fdiv_rn(xyp[1], zeps);
    float invz = __frcp_rn(zeps);          // reference: 1.0 / (z + eps)
    g_xyz[w] = make_float4(x, y, invz, Z);
}

// ---------------- phase A: quadrant-specialized 4x4 tap grid --------------------
// Quadrant (QX,QY): QX=1 means cx = x-px0 >= 0 -> dx in {-1,0,1,2} (dx=-2 column
// provably dead: s2 >= 4+eps -> w<0). Far corner of the 4x4 grid is always dead
// (min s2 = 4.5) and is auto-killed by the ws>0 predicate. 16 slots, 8 iters.
template <int QX, int QY, bool CHECK>
__device__ __forceinline__ void do_taps(float fx, float fy, float invz,
                                        float* accp, float4 f,
                                        int hb, float px0, float py0) {
    const float nhiz = __fmul_rn(invz, -0.5f);   // exact
    const int IDX0 = QX ? -1 : -2;
    const int IDY0 = QY ? -1 : -2;
    const float hbf = (float)hb;
#pragma unroll
    for (int i = 0; i < 8; i++) {
        const int jxb = (2 * i) & 3;             // compile-time
        const int jy  = i >> 1;                  // compile-time
        float dxf = (float)(jxb + IDX0) + hbf;   // const + hbf
        float dyf = (float)(jy + IDY0);          // immediate
        int off = (jy + IDY0) * 256 + jxb + IDX0 + hb;  // const + hb
        float ddx = dxf + fx;
        float ddy = dyf + fy;
        float s2 = __fmaf_rn(ddx, ddx, __fmaf_rn(ddy, ddy, EPSF));
        float dist;
        asm("sqrt.approx.f32 %0, %1;" : "=f"(dist) : "f"(s2));
        // ws = (1 - dist/2) * invz, fused; sign(ws) == sign(1 - dist/2) since invz>0
        float ws = __fmaf_rn(dist, nhiz, invz);
        bool live = ws > 0.f;
        if (CHECK) {
            float px = px0 + dxf;
            float py = py0 + dyf;
            live = live && (px >= 0.f) && (px < (float)Ww) &&
                           (py >= 0.f) && (py < (float)Hh);
        }
        if (live) {
            float* p = accp + ((long)off << 6);
            asm volatile("red.global.add.v4.f32 [%0], {%1,%2,%3,%4};" ::
                         "l"(p), "f"(__fmul_rn(ws, f.x)), "f"(__fmul_rn(ws, f.y)),
                         "f"(__fmul_rn(ws, f.z)), "f"(__fmul_rn(ws, f.w)) : "memory");
        }
    }
}

// -------- splat (fused transpose): block = 64 px, smem-staged feats tile ---------
__global__ void __launch_bounds__(256, 8) splat_kernel(const float* __restrict__ feats,
                                                       int bv0) {
    __shared__ float4 tile[64 * 16];    // [px][cq], cq XOR-swizzled: 16KB
    int tid = threadIdx.x;
    int blk = blockIdx.x;               // [0, BVS*Nn/64)
    int bv = bv0 + (blk >> 10);         // Nn/64 = 1024 blocks per bv
    int n0 = (blk & 1023) * 64;

    // fill smem tile: feats[bv][c][n0..n0+63] -> tile[px][c/4] (swizzled)
    {
        const float* fb = feats + (size_t)bv * Cc * Nn + n0;
        int px = tid & 63;
        int cq0 = tid >> 6;             // 0..3
#pragma unroll
        for (int it = 0; it < 4; it++) {
            int cq = it * 4 + cq0;
            int c = cq * 4;
            float4 v;
            v.x = __ldg(&fb[(size_t)(c + 0) * Nn + px]);
            v.y = __ldg(&fb[(size_t)(c + 1) * Nn + px]);
            v.z = __ldg(&fb[(size_t)(c + 2) * Nn + px]);
            v.w = __ldg(&fb[(size_t)(c + 3) * Nn + px]);
            tile[px * 16 + (cq ^ (px & 15))] = v;
        }
    }
    __syncthreads();

    int lane = tid & 31;
    int wid = tid >> 5;
    int hb = lane >> 4;          // half-warp id: tap parity
    int sl = lane & 15;          // sub-lane: channel group
    float* accbase = g_acc + ((long)bv << 22);
    float* wzbase  = g_wz + ((long)bv << 17);

#pragma unroll 1
    for (int pp = 0; pp < 8; pp++) {
        int p = wid * 8 + pp;
        int w = (bv << 16) + n0 + p;

        float4 pj = __ldg(&g_xyz[w]);    // {x, y, invz, Z} — warp-uniform broadcast
        float Z = pj.w;
        if (!(Z > EPSF)) continue;       // warp-uniform; ref adds w=0 -> no-op
        float x = pj.x, y = pj.y, invz = pj.z;
        float px0 = rintf(x);            // matches jnp.round (half-to-even)
        float py0 = rintf(y);

        float fx = px0 - x;              // feeds approx dist only
        float fy = py0 - y;
        long idx_base = (long)((int)py0) * Ww + (int)px0;

        bool qx = (fx <= 0.f);           // cx >= 0
        bool qy = (fy <= 0.f);
        float nhiz = __fmul_rn(invz, -0.5f);
        bool interior = (px0 >= 2.f) && (px0 <= (float)(Ww - 3)) &&
                        (py0 >= 2.f) && (py0 <= (float)(Hh - 3));

        // ---- phase B: one warp-wide v2 RED covers the 16-slot quadrant grid.
        if (lane < 16) {
            int iqx0 = qx ? -1 : -2;
            int iqy0 = qy ? -1 : -2;
            int jx = lane & 3, jy = lane >> 2;
            float dxf = (float)(jx + iqx0);
            float dyf = (float)(jy + iqy0);
            int offt = (jy + iqy0) * 256 + jx + iqx0;
            float ddx = dxf + fx;
            float ddy = dyf + fy;
            float s2 = __fmaf_rn(ddx, ddx, __fmaf_rn(ddy, ddy, EPSF));
            float dist;
            asm("sqrt.approx.f32 %0, %1;" : "=f"(dist) : "f"(s2));
            float ws = __fmaf_rn(dist, nhiz, invz);   // identical value to phase A
            bool live = ws > 0.f;
            if (!interior) {
                float px = px0 + dxf;
                float py = py0 + dyf;
                live = live && (px >= 0.f) && (px < (float)Ww) &&
                               (py >= 0.f) && (py < (float)Hh);
            }
            if (live) {
                float* q = wzbase + ((idx_base + offt) << 1);
                asm volatile("red.global.add.v2.f32 [%0], {%1,%2};" ::
                             "l"(q), "f"(ws), "f"(__fmul_rn(ws, Z)) : "memory");
            }
        }

        // ---- phase A: feature accumulation (half-warp per tap, v4 per lane).
        float4 f = tile[p * 16 + (sl ^ (p & 15))];
        float* accp = accbase + (idx_base << 6) + 4 * sl;

        if (interior) {
            if (qx) { if (qy) do_taps<1,1,false>(fx,fy,invz,accp,f,hb,px0,py0);
                      else    do_taps<1,0,false>(fx,fy,invz,accp,f,hb,px0,py0); }
            else    { if (qy) do_taps<0,1,false>(fx,fy,invz,accp,f,hb,px0,py0);
                      else    do_taps<0,0,false>(fx,fy,invz,accp,f,hb,px0,py0); }
        } else {
            if (qx) { if (qy) do_taps<1,1,true>(fx,fy,invz,accp,f,hb,px0,py0);
                      else    do_taps<1,0,true>(fx,fy,invz,accp,f,hb,px0,py0); }
            else    { if (qy) do_taps<0,1,true>(fx,fy,invz,accp,f,hb,px0,py0);
                      else    do_taps<0,0,true>(fx,fy,invz,accp,f,hb,px0,py0); }
        }
    }
}

// ---------------- normalize: 64-px tiles, rcp+mul, float4 I/O, per slice ---------
__global__ void __launch_bounds__(256) normalize_kernel(float* __restrict__ out, int bv0) {
    __shared__ float tile[64][65];   // [channel][pixel]
    __shared__ float rws[64];
    __shared__ float zss[64];
    int bv = bv0 + blockIdx.y;
    int n0 = blockIdx.x * 64;
    int tid = threadIdx.x;

    const float4* acc4 = reinterpret_cast<const float4*>(g_acc + (((size_t)bv * Nn + n0) << 6));
#pragma unroll
    for (int r = 0; r < 4; r++) {
        int idx = r * 256 + tid;     // [0, 1024)
        int p = idx >> 4;            // pixel 0..63
        int cq = idx & 15;           // channel quad
        float4 v = acc4[idx];
        tile[4 * cq + 0][p] = v.x;
        tile[4 * cq + 1][p] = v.y;
        tile[4 * cq + 2][p] = v.z;
        tile[4 * cq + 3][p] = v.w;
    }
    if (tid < 64) {
        float2 wzv = reinterpret_cast<const float2*>(g_wz)[(size_t)bv * Nn + n0 + tid];
        rws[tid] = __frcp_rn(__fadd_rn(wzv.x, EPSF));  // rcp+mul vs div: <=2ulp
        zss[tid] = wzv.y;
    }
    __syncthreads();

    float* ob = out + (size_t)bv * (Cc + 1) * Nn + n0;
#pragma unroll
    for (int r = 0; r < 4; r++) {
        int idx = r * 256 + tid;
        int c = idx >> 4;            // channel 0..63
        int j = idx & 15;            // pixel quad
        float4 o;
        o.x = __fmul_rn(tile[c][4 * j + 0], rws[4 * j + 0]);
        o.y = __fmul_rn(tile[c][4 * j + 1], rws[4 * j + 1]);
        o.z = __fmul_rn(tile[c][4 * j + 2], rws[4 * j + 2]);
        o.w = __fmul_rn(tile[c][4 * j + 3], rws[4 * j + 3]);
        reinterpret_cast<float4*>(ob + (size_t)c * Nn)[j] = o;
    }
    if (tid < 16) {
        int j = tid;
        float4 o;
        o.x = __fmul_rn(zss[4 * j + 0], rws[4 * j + 0]);
        o.y = __fmul_rn(zss[4 * j + 1], rws[4 * j + 1]);
        o.z = __fmul_rn(zss[4 * j + 2], rws[4 * j + 2]);
        o.w = __fmul_rn(zss[4 * j + 3], rws[4 * j + 3]);
        reinterpret_cast<float4*>(ob + (size_t)Cc * Nn)[j] = o;
    }
}

// ------- launch: 4 slices x 2bv, 2 streams, splats chained for full efficiency ---
extern "C" void kernel_launch(void* const* d_in, const int* in_sizes, int n_in,
                              void* d_out, int out_size) {
    const float* feats    = (const float*)d_in[0];
    const float* depths   = (const float*)d_in[1];
    const float* K        = (const float*)d_in[2];
    const float* srcRTinv = (const float*)d_in[4];
    const float* dstRT    = (const float*)d_in[5];
    float* out = (float*)d_out;

    // origin stream (legacy default = capture origin)
    build_mats_kernel<<<1, 32>>>(K, srcRTinv, dstRT);
    cudaEventRecord(g_sc.fork, 0);
    cudaStreamWaitEvent(g_sc.s[0], g_sc.fork, 0);
    cudaStreamWaitEvent(g_sc.s[1], g_sc.fork, 0);

    for (int sl = 0; sl < NSLICE; sl++) {
        cudaStream_t st = g_sc.s[sl & 1];
        int bv0 = sl * BVS;
        proj_kernel<<<(BVS * Nn) / 256, 256, 0, st>>>(depths, bv0);
        if (sl > 0) cudaStreamWaitEvent(st, g_sc.esp[sl - 1], 0);  // serialize splats
        splat_kernel<<<(BVS * Nn) / 64, 256, 0, st>>>(feats, bv0);
        cudaEventRecord(g_sc.esp[sl], st);
        normalize_kernel<<<dim3(Nn / 64, BVS), 256, 0, st>>>(out, bv0);
    }

    cudaEventRecord(g_sc.join[0], g_sc.s[0]);
    cudaEventRecord(g_sc.join[1], g_sc.s[1]);
    cudaStreamWaitEvent(0, g_sc.join[0], 0);
    cudaStreamWaitEvent(0, g_sc.join[1], 0);
}